// round 2
// baseline (speedup 1.0000x reference)
#include <cuda_runtime.h>
#include <math.h>

#define BATCH 128
#define LQv   128
#define LAv   512
#define EMBD  300
#define FILT  400

// ---- scratch (static __device__: no allocations allowed) ----
__device__ float    g_Q[BATCH * LQv * FILT];   // [b*LQ+t][f]
__device__ float    g_A[BATCH * LAv * FILT];   // [b*LA+t][f]
__device__ float    g_T[BATCH * LQv * FILT];   // [b*LQ+q][g]
__device__ unsigned g_mq[BATCH * LQv];         // encoded float max over a
__device__ unsigned g_ma[BATCH * LAv];         // encoded float max over q

__device__ __forceinline__ unsigned enc_f(float f) {
    int i = __float_as_int(f);
    return (unsigned)(i ^ ((i >> 31) | 0x80000000));
}
__device__ __forceinline__ float dec_f(unsigned u) {
    int i = (u & 0x80000000u) ? (int)(u ^ 0x80000000u) : ~(int)u;
    return __int_as_float(i);
}

// ---------------------------------------------------------------------------
// 0) init the max buffers
// ---------------------------------------------------------------------------
__global__ void init_max_kernel() {
    int idx = blockIdx.x * blockDim.x + threadIdx.x;
    unsigned v = enc_f(-2.0f);
    if (idx < BATCH * LQv) g_mq[idx] = v;
    if (idx < BATCH * LAv) g_ma[idx] = v;
}

// ---------------------------------------------------------------------------
// 1) fused gather + conv1d(K=3, pad=1) as GEMM.
//    out[(b*L+t)*400 + f] = bias[f] + sum_{k,e} w[f,e,k] * emb[tok[b,t+k-1], e]
//    Tile: 64 tokens x 64 filters, 256 threads, 4f x 4t per thread.
// ---------------------------------------------------------------------------
#define CBT 64
#define CBF 64
#define CEC 30

__global__ __launch_bounds__(256) void conv_encode_kernel(
    const int* __restrict__ tok, const float* __restrict__ emb,
    const float* __restrict__ cw, const float* __restrict__ cb,
    int is_q, int L)
{
    __shared__ int s_tok[CBT + 2];
    __shared__ __align__(16) float Esh[CBT + 2][33];
    __shared__ __align__(16) float Wsh[3][CEC][CBF];

    float* __restrict__ dst = is_q ? g_Q : g_A;

    const int b  = blockIdx.z;
    const int t0 = blockIdx.x * CBT;
    const int f0 = blockIdx.y * CBF;
    const int tid = threadIdx.x;
    const int tf = tid & 15;   // filter group (x4)
    const int tt = tid >> 4;   // token group (x4)

    for (int r = tid; r < CBT + 2; r += 256) {
        int tg = t0 + r - 1;
        s_tok[r] = (tg >= 0 && tg < L) ? tok[b * L + tg] : -1;
    }
    __syncthreads();

    float acc[4][4];
#pragma unroll
    for (int f = 0; f < 4; f++)
#pragma unroll
        for (int t = 0; t < 4; t++) acc[f][t] = 0.0f;

    for (int ec = 0; ec < EMBD; ec += CEC) {
        // stage embedding chunk [66 rows][30 dims]
        for (int i = tid; i < (CBT + 2) * CEC; i += 256) {
            int r  = i / CEC;
            int eo = i % CEC;
            int tg = s_tok[r];
            Esh[r][eo] = (tg >= 0) ? emb[(size_t)tg * EMBD + ec + eo] : 0.0f;
        }
        // stage weight chunk transposed to [k][e][f]  (cw layout: [f][e][k])
        for (int i = tid; i < CBF * (CEC * 3); i += 256) {
            int f = i / (CEC * 3);
            int j = i % (CEC * 3);           // j = e_off*3 + k (contiguous in cw row)
            float v = (f0 + f < FILT) ? cw[(size_t)(f0 + f) * (EMBD * 3) + ec * 3 + j] : 0.0f;
            Wsh[j % 3][j / 3][f] = v;
        }
        __syncthreads();

#pragma unroll 6
        for (int eo = 0; eo < CEC; eo++) {
            float ev[6];
#pragma unroll
            for (int i = 0; i < 6; i++) ev[i] = Esh[tt * 4 + i][eo];
#pragma unroll
            for (int k = 0; k < 3; k++) {
                float4 w4 = *(const float4*)&Wsh[k][eo][tf * 4];
                float wf[4] = {w4.x, w4.y, w4.z, w4.w};
#pragma unroll
                for (int f = 0; f < 4; f++)
#pragma unroll
                    for (int t = 0; t < 4; t++)
                        acc[f][t] += wf[f] * ev[t + k];
            }
        }
        __syncthreads();
    }

#pragma unroll
    for (int f = 0; f < 4; f++) {
        int fg = f0 + tf * 4 + f;
        if (fg < FILT) {
            float bias = cb[fg];
#pragma unroll
            for (int t = 0; t < 4; t++) {
                int tg = t0 + tt * 4 + t;
                dst[((size_t)b * L + tg) * FILT + fg] = acc[f][t] + bias;
            }
        }
    }
}

// ---------------------------------------------------------------------------
// 2) T[b] = Qm[b] (128x400, row-major) @ W (400x400, row-major)
// ---------------------------------------------------------------------------
__global__ __launch_bounds__(256) void gemm_T_kernel(const float* __restrict__ W)
{
    __shared__ float Ash[64][17];                 // [m][k]
    __shared__ __align__(16) float Bsh[16][64];   // [k][n]

    const int b  = blockIdx.z;
    const int n0 = blockIdx.x * 64;
    const int m0 = blockIdx.y * 64;
    const int tid = threadIdx.x;
    const int tx = tid & 15, ty = tid >> 4;

    float acc[4][4];
#pragma unroll
    for (int i = 0; i < 4; i++)
#pragma unroll
        for (int j = 0; j < 4; j++) acc[i][j] = 0.0f;

    for (int kk = 0; kk < FILT; kk += 16) {
        for (int i = tid; i < 64 * 16; i += 256) {
            int m = i >> 4, k = i & 15;
            Ash[m][k] = g_Q[((size_t)b * LQv + m0 + m) * FILT + kk + k];
        }
        for (int i = tid; i < 16 * 64; i += 256) {
            int k = i >> 6, n = i & 63;
            Bsh[k][n] = (n0 + n < FILT) ? W[(size_t)(kk + k) * FILT + n0 + n] : 0.0f;
        }
        __syncthreads();
#pragma unroll
        for (int k = 0; k < 16; k++) {
            float a[4];
#pragma unroll
            for (int i = 0; i < 4; i++) a[i] = Ash[ty * 4 + i][k];
            float4 b4 = *(const float4*)&Bsh[k][tx * 4];
            float bb[4] = {b4.x, b4.y, b4.z, b4.w};
#pragma unroll
            for (int i = 0; i < 4; i++)
#pragma unroll
                for (int j = 0; j < 4; j++) acc[i][j] += a[i] * bb[j];
        }
        __syncthreads();
    }

#pragma unroll
    for (int j = 0; j < 4; j++) {
        int n = n0 + tx * 4 + j;
        if (n < FILT) {
#pragma unroll
            for (int i = 0; i < 4; i++)
                g_T[((size_t)b * LQv + m0 + ty * 4 + i) * FILT + n] = acc[i][j];
        }
    }
}

// ---------------------------------------------------------------------------
// 3) G = tanh(T @ A^T), fused row/col max -> g_mq / g_ma. G never stored.
//    M=128 (q), N=512 (a), K=400. Both operands K-major (NT GEMM).
// ---------------------------------------------------------------------------
__global__ __launch_bounds__(256) void gemm_G_kernel()
{
    __shared__ float Ash[64][17];   // [q][k]
    __shared__ float Bsh[64][17];   // [a][k]
    __shared__ unsigned srow[64], scol[64];

    const int b  = blockIdx.z;
    const int a0 = blockIdx.x * 64;
    const int q0 = blockIdx.y * 64;
    const int tid = threadIdx.x;
    const int tx = tid & 15, ty = tid >> 4;

    float acc[4][4];
#pragma unroll
    for (int i = 0; i < 4; i++)
#pragma unroll
        for (int j = 0; j < 4; j++) acc[i][j] = 0.0f;

    for (int kk = 0; kk < FILT; kk += 16) {
        for (int i = tid; i < 64 * 16; i += 256) {
            int m = i >> 4, k = i & 15;
            Ash[m][k] = g_T[((size_t)b * LQv + q0 + m) * FILT + kk + k];
        }
        for (int i = tid; i < 64 * 16; i += 256) {
            int n = i >> 4, k = i & 15;
            Bsh[n][k] = g_A[((size_t)b * LAv + a0 + n) * FILT + kk + k];
        }
        __syncthreads();
#pragma unroll
        for (int k = 0; k < 16; k++) {
            float a[4], bb[4];
#pragma unroll
            for (int i = 0; i < 4; i++) a[i] = Ash[ty * 4 + i][k];
#pragma unroll
            for (int j = 0; j < 4; j++) bb[j] = Bsh[tx * 4 + j][k];
#pragma unroll
            for (int i = 0; i < 4; i++)
#pragma unroll
                for (int j = 0; j < 4; j++) acc[i][j] += a[i] * bb[j];
        }
        __syncthreads();
    }

    // tanh + tile max reduction
    if (tid < 64) { srow[tid] = enc_f(-2.0f); scol[tid] = enc_f(-2.0f); }
    __syncthreads();

    float tv[4][4];
#pragma unroll
    for (int i = 0; i < 4; i++)
#pragma unroll
        for (int j = 0; j < 4; j++) tv[i][j] = tanhf(acc[i][j]);

#pragma unroll
    for (int i = 0; i < 4; i++) {
        float rm = fmaxf(fmaxf(tv[i][0], tv[i][1]), fmaxf(tv[i][2], tv[i][3]));
        atomicMax(&srow[ty * 4 + i], enc_f(rm));
    }
#pragma unroll
    for (int j = 0; j < 4; j++) {
        float cm = fmaxf(fmaxf(tv[0][j], tv[1][j]), fmaxf(tv[2][j], tv[3][j]));
        atomicMax(&scol[tx * 4 + j], enc_f(cm));
    }
    __syncthreads();

    if (tid < 64) {
        atomicMax(&g_mq[b * LQv + q0 + tid], srow[tid]);
        atomicMax(&g_ma[b * LAv + a0 + tid], scol[tid]);
    }
}

// ---------------------------------------------------------------------------
// 4) per-batch: softmax over maxes, pooled vectors, cosine similarity
// ---------------------------------------------------------------------------
__global__ __launch_bounds__(256) void finalize_kernel(float* __restrict__ out)
{
    __shared__ float sq[LQv], sa[LAv], rq[FILT], ra[FILT];
    __shared__ float smax[2], ssum[2];
    __shared__ float sd[256], sx[256], sy[256];

    const int b = blockIdx.x;
    const int tid = threadIdx.x;

    for (int q = tid; q < LQv; q += 256) sq[q] = dec_f(g_mq[b * LQv + q]);
    for (int a = tid; a < LAv; a += 256) sa[a] = dec_f(g_ma[b * LAv + a]);
    __syncthreads();

    if (tid == 0) {
        float m = -1e30f;
        for (int q = 0; q < LQv; q++) m = fmaxf(m, sq[q]);
        smax[0] = m;
    } else if (tid == 32) {
        float m = -1e30f;
        for (int a = 0; a < LAv; a++) m = fmaxf(m, sa[a]);
        smax[1] = m;
    }
    __syncthreads();
    for (int q = tid; q < LQv; q += 256) sq[q] = expf(sq[q] - smax[0]);
    for (int a = tid; a < LAv; a += 256) sa[a] = expf(sa[a] - smax[1]);
    __syncthreads();
    if (tid == 0) {
        float s = 0.0f;
        for (int q = 0; q < LQv; q++) s += sq[q];
        ssum[0] = s;
    } else if (tid == 32) {
        float s = 0.0f;
        for (int a = 0; a < LAv; a++) s += sa[a];
        ssum[1] = s;
    }
    __syncthreads();
    {
        float invq = 1.0f / ssum[0], inva = 1.0f / ssum[1];
        for (int q = tid; q < LQv; q += 256) sq[q] *= invq;
        for (int a = tid; a < LAv; a += 256) sa[a] *= inva;
    }
    __syncthreads();

    // rQ[f] = sum_q Qm[q,f] * roQ[q];  rA[f] = sum_a Am[a,f] * roA[a]
    for (int f = tid; f < FILT; f += 256) {
        const float* qp = g_Q + (size_t)b * LQv * FILT + f;
        float acc = 0.0f;
        for (int q = 0; q < LQv; q++) acc += qp[(size_t)q * FILT] * sq[q];
        rq[f] = acc;
    }
    for (int f = tid; f < FILT; f += 256) {
        const float* ap = g_A + (size_t)b * LAv * FILT + f;
        float acc = 0.0f;
        for (int a = 0; a < LAv; a++) acc += ap[(size_t)a * FILT] * sa[a];
        ra[f] = acc;
    }
    __syncthreads();

    float d = 0.0f, x = 0.0f, y = 0.0f;
    for (int f = tid; f < FILT; f += 256) {
        d += rq[f] * ra[f];
        x += rq[f] * rq[f];
        y += ra[f] * ra[f];
    }
    sd[tid] = d; sx[tid] = x; sy[tid] = y;
    __syncthreads();
    if (tid == 0) {
        float D = 0.0f, X = 0.0f, Y = 0.0f;
        for (int i = 0; i < 256; i++) { D += sd[i]; X += sx[i]; Y += sy[i]; }
        float nq = fmaxf(sqrtf(X), 1e-8f);
        float na = fmaxf(sqrtf(Y), 1e-8f);
        out[b] = D / (nq * na);
    }
}

// ---------------------------------------------------------------------------
// launch
// ---------------------------------------------------------------------------
extern "C" void kernel_launch(void* const* d_in, const int* in_sizes, int n_in,
                              void* d_out, int out_size)
{
    const int*   questions = (const int*)d_in[0];
    const int*   answers   = (const int*)d_in[1];
    const float* emb       = (const float*)d_in[2];
    const float* conv_w    = (const float*)d_in[3];
    const float* conv_b    = (const float*)d_in[4];
    const float* W         = (const float*)d_in[5];
    float*       out       = (float*)d_out;

    (void)in_sizes; (void)n_in; (void)out_size;

    init_max_kernel<<<(BATCH * LAv + 255) / 256, 256>>>();

    conv_encode_kernel<<<dim3(LQv / CBT, (FILT + CBF - 1) / CBF, BATCH), 256>>>(
        questions, emb, conv_w, conv_b, 1, LQv);
    conv_encode_kernel<<<dim3(LAv / CBT, (FILT + CBF - 1) / CBF, BATCH), 256>>>(
        answers, emb, conv_w, conv_b, 0, LAv);

    gemm_T_kernel<<<dim3((FILT + 63) / 64, LQv / 64, BATCH), 256>>>(W);
    gemm_G_kernel<<<dim3(LAv / 64, LQv / 64, BATCH), 256>>>();

    finalize_kernel<<<BATCH, 256>>>(out);
}

// round 3
// speedup vs baseline: 2.6606x; 2.6606x over previous
#include <cuda_runtime.h>
#include <math.h>

#define BATCH 128
#define LQv   128
#define LAv   512
#define EMBD  300
#define FILT  400
#define EPAD  320
#define KCONV (3 * EPAD)   // 960

// ---- scratch (static __device__: no allocations allowed) ----
__device__ float    g_Q[BATCH * LQv * FILT];     // [b*LQ+t][f]
__device__ float    g_A[BATCH * LAv * FILT];     // [b*LA+t][f]
__device__ float    g_T[BATCH * LQv * FILT];     // [b*LQ+q][g]
__device__ unsigned g_Bw[KCONV * FILT];          // conv weights, [k'][f], tf32 bits
__device__ unsigned g_mq[BATCH * LQv];
__device__ unsigned g_ma[BATCH * LAv];

__device__ __forceinline__ unsigned enc_f(float f) {
    int i = __float_as_int(f);
    return (unsigned)(i ^ ((i >> 31) | 0x80000000));
}
__device__ __forceinline__ float dec_f(unsigned u) {
    int i = (u & 0x80000000u) ? (int)(u ^ 0x80000000u) : ~(int)u;
    return __int_as_float(i);
}
__device__ __forceinline__ unsigned f2tf(float f) {
    unsigned u;
    asm("cvt.rna.tf32.f32 %0, %1;" : "=r"(u) : "f"(f));
    return u;
}
__device__ __forceinline__ void mma8(float* c, const unsigned* a, const unsigned* b) {
    asm("mma.sync.aligned.m16n8k8.row.col.f32.tf32.tf32.f32 "
        "{%0,%1,%2,%3},{%4,%5,%6,%7},{%8,%9},{%0,%1,%2,%3};"
        : "+f"(c[0]), "+f"(c[1]), "+f"(c[2]), "+f"(c[3])
        : "r"(a[0]), "r"(a[1]), "r"(a[2]), "r"(a[3]), "r"(b[0]), "r"(b[1]));
}

// ---------------------------------------------------------------------------
// 0) init max buffers
// ---------------------------------------------------------------------------
__global__ void init_max_kernel() {
    int idx = blockIdx.x * blockDim.x + threadIdx.x;
    unsigned v = enc_f(-2.0f);
    if (idx < BATCH * LQv) g_mq[idx] = v;
    if (idx < BATCH * LAv) g_ma[idx] = v;
}

// ---------------------------------------------------------------------------
// 0b) pre-transpose conv weights: g_Bw[(koff*EPAD+e)*400 + f] = tf32(cw[f][e][koff])
// ---------------------------------------------------------------------------
__global__ void transpose_w_kernel(const float* __restrict__ cw) {
    int idx = blockIdx.x * blockDim.x + threadIdx.x;
    if (idx >= KCONV * FILT) return;
    int kp = idx / FILT, n = idx % FILT;
    int koff = kp / EPAD, e = kp % EPAD;
    float v = (e < EMBD) ? cw[(size_t)n * (EMBD * 3) + e * 3 + koff] : 0.0f;
    g_Bw[idx] = f2tf(v);
}

// ---------------------------------------------------------------------------
// 1) conv encode via tf32 mma. Block tile 128(tok) x 80(filt), K'=960.
//    8 warps (4m x 2n), warp tile 32x40. KC=32 per stage.
// ---------------------------------------------------------------------------
#define C_KC 32
#define C_AP 136
#define C_BP 88

__global__ __launch_bounds__(256) void conv_encode_kernel(
    const int* __restrict__ tok, const float* __restrict__ emb,
    const float* __restrict__ cb, int is_q, int L)
{
    __shared__ int s_tok[130];
    __shared__ unsigned As[C_KC][C_AP];   // [k][m]
    __shared__ unsigned Bs[C_KC][C_BP];   // [k][n]

    float* __restrict__ dst = is_q ? g_Q : g_A;

    const int b  = blockIdx.z;
    const int t0 = blockIdx.x * 128;
    const int n0 = blockIdx.y * 80;
    const int tid  = threadIdx.x;
    const int wid  = tid >> 5, lane = tid & 31;
    const int g    = lane >> 2, tig = lane & 3;
    const int wm   = wid & 3,  wn  = wid >> 2;   // 4 x 2 warps
    const int mwb  = wm * 32;
    const int nwb  = wn * 40;

    for (int r = tid; r < 130; r += 256) {
        int tg = t0 + r - 1;
        s_tok[r] = (tg >= 0 && tg < L) ? tok[b * L + tg] : -1;
    }
    __syncthreads();

    float c[2][5][4];
#pragma unroll
    for (int i = 0; i < 2; i++)
#pragma unroll
        for (int j = 0; j < 5; j++)
#pragma unroll
            for (int k = 0; k < 4; k++) c[i][j][k] = 0.0f;

    for (int koff = 0; koff < 3; koff++) {
        for (int ec = 0; ec < EPAD; ec += C_KC) {
            // stage A: As[kc][m] = tf32(emb[tok[t0+m+koff-1]][ec+kc])
#pragma unroll
            for (int it = 0; it < 4; it++) {
                int i = tid + it * 256;          // 1024 items: 128 m x 8 k4
                int m = i >> 3, k4 = i & 7;
                int e = ec + k4 * 4;
                int trow = s_tok[m + koff];
                float4 v = make_float4(0.f, 0.f, 0.f, 0.f);
                if (trow >= 0 && e < EMBD)
                    v = *(const float4*)&emb[(size_t)trow * EMBD + e];
                As[k4 * 4 + 0][m] = f2tf(v.x);
                As[k4 * 4 + 1][m] = f2tf(v.y);
                As[k4 * 4 + 2][m] = f2tf(v.z);
                As[k4 * 4 + 3][m] = f2tf(v.w);
            }
            // stage B: raw copy (already tf32 bits)
            {
                int kg0 = koff * EPAD + ec;
#pragma unroll
                for (int it = 0; it < 10; it++) {
                    int i = tid + it * 256;      // 2560 items: 32 kc x 80 n
                    int kc = i / 80, n = i - kc * 80;
                    Bs[kc][n] = g_Bw[(size_t)(kg0 + kc) * FILT + n0 + n];
                }
            }
            __syncthreads();

#pragma unroll
            for (int kb = 0; kb < C_KC / 8; kb++) {
                int kk = kb * 8;
                unsigned a[2][4];
#pragma unroll
                for (int ms = 0; ms < 2; ms++) {
                    int rb = mwb + ms * 16 + g;
                    a[ms][0] = As[kk + tig][rb];
                    a[ms][1] = As[kk + tig][rb + 8];
                    a[ms][2] = As[kk + tig + 4][rb];
                    a[ms][3] = As[kk + tig + 4][rb + 8];
                }
#pragma unroll
                for (int ns = 0; ns < 5; ns++) {
                    unsigned bf[2];
                    int nb = nwb + ns * 8 + g;
                    bf[0] = Bs[kk + tig][nb];
                    bf[1] = Bs[kk + tig + 4][nb];
                    mma8(c[0][ns], a[0], bf);
                    mma8(c[1][ns], a[1], bf);
                }
            }
            __syncthreads();
        }
    }

    // epilogue: + bias, store
#pragma unroll
    for (int ms = 0; ms < 2; ms++) {
#pragma unroll
        for (int ns = 0; ns < 5; ns++) {
            int col = n0 + nwb + ns * 8 + 2 * tig;
            float2 bias = *(const float2*)&cb[col];
            int row0 = t0 + mwb + ms * 16 + g;
            float2 v0 = make_float2(c[ms][ns][0] + bias.x, c[ms][ns][1] + bias.y);
            float2 v1 = make_float2(c[ms][ns][2] + bias.x, c[ms][ns][3] + bias.y);
            *(float2*)&dst[((size_t)b * L + row0) * FILT + col] = v0;
            *(float2*)&dst[((size_t)b * L + row0 + 8) * FILT + col] = v1;
        }
    }
}

// ---------------------------------------------------------------------------
// 2) T = Qm @ W : M=128, N=400 (5 x 80), K=400. KC=40.
// ---------------------------------------------------------------------------
#define T_KC 40
#define T_AP 136
#define T_BP 88

__global__ __launch_bounds__(256) void gemm_T_kernel(const float* __restrict__ W)
{
    __shared__ unsigned As[T_KC][T_AP];
    __shared__ unsigned Bs[T_KC][T_BP];

    const int b  = blockIdx.z;
    const int n0 = blockIdx.x * 80;
    const int tid  = threadIdx.x;
    const int wid  = tid >> 5, lane = tid & 31;
    const int g    = lane >> 2, tig = lane & 3;
    const int wm   = wid & 3,  wn  = wid >> 2;
    const int mwb  = wm * 32, nwb = wn * 40;

    float c[2][5][4];
#pragma unroll
    for (int i = 0; i < 2; i++)
#pragma unroll
        for (int j = 0; j < 5; j++)
#pragma unroll
            for (int k = 0; k < 4; k++) c[i][j][k] = 0.0f;

    for (int k0 = 0; k0 < FILT; k0 += T_KC) {
        // A: g_Q rows -> As[k][m]
#pragma unroll
        for (int it = 0; it < 5; it++) {
            int i = tid + it * 256;          // 1280: 128 m x 10 k4
            int m = i / 10, k4 = i - m * 10;
            float4 v = *(const float4*)&g_Q[((size_t)b * LQv + m) * FILT + k0 + k4 * 4];
            As[k4 * 4 + 0][m] = f2tf(v.x);
            As[k4 * 4 + 1][m] = f2tf(v.y);
            As[k4 * 4 + 2][m] = f2tf(v.z);
            As[k4 * 4 + 3][m] = f2tf(v.w);
        }
        // B: W rows -> Bs[k][n]
        for (int i = tid; i < T_KC * 80; i += 256) {
            int kc = i / 80, n = i - kc * 80;
            Bs[kc][n] = f2tf(W[(size_t)(k0 + kc) * FILT + n0 + n]);
        }
        __syncthreads();

#pragma unroll
        for (int kb = 0; kb < T_KC / 8; kb++) {
            int kk = kb * 8;
            unsigned a[2][4];
#pragma unroll
            for (int ms = 0; ms < 2; ms++) {
                int rb = mwb + ms * 16 + g;
                a[ms][0] = As[kk + tig][rb];
                a[ms][1] = As[kk + tig][rb + 8];
                a[ms][2] = As[kk + tig + 4][rb];
                a[ms][3] = As[kk + tig + 4][rb + 8];
            }
#pragma unroll
            for (int ns = 0; ns < 5; ns++) {
                unsigned bf[2];
                int nb = nwb + ns * 8 + g;
                bf[0] = Bs[kk + tig][nb];
                bf[1] = Bs[kk + tig + 4][nb];
                mma8(c[0][ns], a[0], bf);
                mma8(c[1][ns], a[1], bf);
            }
        }
        __syncthreads();
    }

#pragma unroll
    for (int ms = 0; ms < 2; ms++) {
#pragma unroll
        for (int ns = 0; ns < 5; ns++) {
            int col = n0 + nwb + ns * 8 + 2 * tig;
            int row0 = mwb + ms * 16 + g;
            *(float2*)&g_T[((size_t)b * LQv + row0) * FILT + col] =
                make_float2(c[ms][ns][0], c[ms][ns][1]);
            *(float2*)&g_T[((size_t)b * LQv + row0 + 8) * FILT + col] =
                make_float2(c[ms][ns][2], c[ms][ns][3]);
        }
    }
}

// ---------------------------------------------------------------------------
// 3) G = tanh(T @ A^T) fused row/col max. M=128(q), N=512 (8 x 64), K=400.
//    8 warps (4m x 2n), warp 32x32. KC=40.
// ---------------------------------------------------------------------------
#define G_KC 40
#define G_AP 136
#define G_BP 72

__global__ __launch_bounds__(256) void gemm_G_kernel()
{
    __shared__ unsigned As[G_KC][G_AP];   // [k][q]
    __shared__ unsigned Bs[G_KC][G_BP];   // [k][a]
    __shared__ unsigned srow[128], scol[64];

    const int b  = blockIdx.z;
    const int a0 = blockIdx.x * 64;
    const int tid  = threadIdx.x;
    const int wid  = tid >> 5, lane = tid & 31;
    const int g    = lane >> 2, tig = lane & 3;
    const int wm   = wid & 3,  wn  = wid >> 2;
    const int mwb  = wm * 32, nwb = wn * 32;

    if (tid < 128) srow[tid] = enc_f(-2.0f);
    if (tid < 64)  scol[tid] = enc_f(-2.0f);

    float c[2][4][4];
#pragma unroll
    for (int i = 0; i < 2; i++)
#pragma unroll
        for (int j = 0; j < 4; j++)
#pragma unroll
            for (int k = 0; k < 4; k++) c[i][j][k] = 0.0f;

    for (int k0 = 0; k0 < FILT; k0 += G_KC) {
        __syncthreads();
#pragma unroll
        for (int it = 0; it < 5; it++) {
            int i = tid + it * 256;          // 1280: 128 q x 10 k4
            int m = i / 10, k4 = i - m * 10;
            float4 v = *(const float4*)&g_T[((size_t)b * LQv + m) * FILT + k0 + k4 * 4];
            As[k4 * 4 + 0][m] = f2tf(v.x);
            As[k4 * 4 + 1][m] = f2tf(v.y);
            As[k4 * 4 + 2][m] = f2tf(v.z);
            As[k4 * 4 + 3][m] = f2tf(v.w);
        }
        for (int i = tid; i < 640; i += 256) {   // 64 a x 10 k4
            int n = i / 10, k4 = i - n * 10;
            float4 v = *(const float4*)&g_A[((size_t)b * LAv + a0 + n) * FILT + k0 + k4 * 4];
            Bs[k4 * 4 + 0][n] = f2tf(v.x);
            Bs[k4 * 4 + 1][n] = f2tf(v.y);
            Bs[k4 * 4 + 2][n] = f2tf(v.z);
            Bs[k4 * 4 + 3][n] = f2tf(v.w);
        }
        __syncthreads();

#pragma unroll
        for (int kb = 0; kb < G_KC / 8; kb++) {
            int kk = kb * 8;
            unsigned a[2][4];
#pragma unroll
            for (int ms = 0; ms < 2; ms++) {
                int rb = mwb + ms * 16 + g;
                a[ms][0] = As[kk + tig][rb];
                a[ms][1] = As[kk + tig][rb + 8];
                a[ms][2] = As[kk + tig + 4][rb];
                a[ms][3] = As[kk + tig + 4][rb + 8];
            }
#pragma unroll
            for (int ns = 0; ns < 4; ns++) {
                unsigned bf[2];
                int nb = nwb + ns * 8 + g;
                bf[0] = Bs[kk + tig][nb];
                bf[1] = Bs[kk + tig + 4][nb];
                mma8(c[0][ns], a[0], bf);
                mma8(c[1][ns], a[1], bf);
            }
        }
    }
    __syncthreads();

    // tanh + per-thread partial reductions + shared atomics
    float tv[2][4][4];
#pragma unroll
    for (int ms = 0; ms < 2; ms++)
#pragma unroll
        for (int ns = 0; ns < 4; ns++)
#pragma unroll
            for (int k = 0; k < 4; k++) tv[ms][ns][k] = tanhf(c[ms][ns][k]);

#pragma unroll
    for (int ms = 0; ms < 2; ms++) {
        float r0 = -2.0f, r1 = -2.0f;
#pragma unroll
        for (int ns = 0; ns < 4; ns++) {
            r0 = fmaxf(r0, fmaxf(tv[ms][ns][0], tv[ms][ns][1]));
            r1 = fmaxf(r1, fmaxf(tv[ms][ns][2], tv[ms][ns][3]));
        }
        atomicMax(&srow[mwb + ms * 16 + g],     enc_f(r0));
        atomicMax(&srow[mwb + ms * 16 + g + 8], enc_f(r1));
    }
#pragma unroll
    for (int ns = 0; ns < 4; ns++) {
        float c0 = -2.0f, c1 = -2.0f;
#pragma unroll
        for (int ms = 0; ms < 2; ms++) {
            c0 = fmaxf(c0, fmaxf(tv[ms][ns][0], tv[ms][ns][2]));
            c1 = fmaxf(c1, fmaxf(tv[ms][ns][1], tv[ms][ns][3]));
        }
        int nb = nwb + ns * 8 + 2 * tig;
        atomicMax(&scol[nb],     enc_f(c0));
        atomicMax(&scol[nb + 1], enc_f(c1));
    }
    __syncthreads();

    if (tid < 128) atomicMax(&g_mq[b * LQv + tid], srow[tid]);
    if (tid < 64)  atomicMax(&g_ma[b * LAv + a0 + tid], scol[tid]);
}

// ---------------------------------------------------------------------------
// 4) per-batch finalize (softmax over maxes, pooling, cosine)
// ---------------------------------------------------------------------------
__global__ __launch_bounds__(256) void finalize_kernel(float* __restrict__ out)
{
    __shared__ float sq[LQv], sa[LAv], rq[FILT], ra[FILT];
    __shared__ float smax[2], ssum[2];
    __shared__ float sd[256], sx[256], sy[256];

    const int b = blockIdx.x;
    const int tid = threadIdx.x;

    for (int q = tid; q < LQv; q += 256) sq[q] = dec_f(g_mq[b * LQv + q]);
    for (int a = tid; a < LAv; a += 256) sa[a] = dec_f(g_ma[b * LAv + a]);
    __syncthreads();

    if (tid == 0) {
        float m = -1e30f;
        for (int q = 0; q < LQv; q++) m = fmaxf(m, sq[q]);
        smax[0] = m;
    } else if (tid == 32) {
        float m = -1e30f;
        for (int a = 0; a < LAv; a++) m = fmaxf(m, sa[a]);
        smax[1] = m;
    }
    __syncthreads();
    for (int q = tid; q < LQv; q += 256) sq[q] = expf(sq[q] - smax[0]);
    for (int a = tid; a < LAv; a += 256) sa[a] = expf(sa[a] - smax[1]);
    __syncthreads();
    if (tid == 0) {
        float s = 0.0f;
        for (int q = 0; q < LQv; q++) s += sq[q];
        ssum[0] = s;
    } else if (tid == 32) {
        float s = 0.0f;
        for (int a = 0; a < LAv; a++) s += sa[a];
        ssum[1] = s;
    }
    __syncthreads();
    {
        float invq = 1.0f / ssum[0], inva = 1.0f / ssum[1];
        for (int q = tid; q < LQv; q += 256) sq[q] *= invq;
        for (int a = tid; a < LAv; a += 256) sa[a] *= inva;
    }
    __syncthreads();

    for (int f = tid; f < FILT; f += 256) {
        const float* qp = g_Q + (size_t)b * LQv * FILT + f;
        float acc = 0.0f;
        for (int q = 0; q < LQv; q++) acc += qp[(size_t)q * FILT] * sq[q];
        rq[f] = acc;
    }
    for (int f = tid; f < FILT; f += 256) {
        const float* ap = g_A + (size_t)b * LAv * FILT + f;
        float acc = 0.0f;
        for (int a = 0; a < LAv; a++) acc += ap[(size_t)a * FILT] * sa[a];
        ra[f] = acc;
    }
    __syncthreads();

    float d = 0.0f, x = 0.0f, y = 0.0f;
    for (int f = tid; f < FILT; f += 256) {
        d += rq[f] * ra[f];
        x += rq[f] * rq[f];
        y += ra[f] * ra[f];
    }
    sd[tid] = d; sx[tid] = x; sy[tid] = y;
    __syncthreads();
    if (tid == 0) {
        float D = 0.0f, X = 0.0f, Y = 0.0f;
        for (int i = 0; i < 256; i++) { D += sd[i]; X += sx[i]; Y += sy[i]; }
        float nq = fmaxf(sqrtf(X), 1e-8f);
        float na = fmaxf(sqrtf(Y), 1e-8f);
        out[b] = D / (nq * na);
    }
}

// ---------------------------------------------------------------------------
// launch
// ---------------------------------------------------------------------------
extern "C" void kernel_launch(void* const* d_in, const int* in_sizes, int n_in,
                              void* d_out, int out_size)
{
    const int*   questions = (const int*)d_in[0];
    const int*   answers   = (const int*)d_in[1];
    const float* emb       = (const float*)d_in[2];
    const float* conv_w    = (const float*)d_in[3];
    const float* conv_b    = (const float*)d_in[4];
    const float* W         = (const float*)d_in[5];
    float*       out       = (float*)d_out;

    (void)in_sizes; (void)n_in; (void)out_size;

    init_max_kernel<<<(BATCH * LAv + 255) / 256, 256>>>();
    transpose_w_kernel<<<(KCONV * FILT + 255) / 256, 256>>>(conv_w);

    conv_encode_kernel<<<dim3(LQv / 128, FILT / 80, BATCH), 256>>>(
        questions, emb, conv_b, 1, LQv);
    conv_encode_kernel<<<dim3(LAv / 128, FILT / 80, BATCH), 256>>>(
        answers, emb, conv_b, 0, LAv);

    gemm_T_kernel<<<dim3(FILT / 80, 1, BATCH), 256>>>(W);
    gemm_G_kernel<<<dim3(LAv / 64, 1, BATCH), 256>>>();

    finalize_kernel<<<BATCH, 256>>>(out);
}

// round 4
// speedup vs baseline: 4.9521x; 1.8612x over previous
#include <cuda_runtime.h>
#include <math.h>

#define BATCH 128
#define LQv   128
#define LAv   512
#define EMBD  300
#define FILT  400
#define EPAD  320
#define KCONV (3 * EPAD)   // 960

// ---- scratch (static __device__: no allocations allowed) ----
__device__ float    g_Q[BATCH * LQv * FILT];     // [b*LQ+t][f]
__device__ float    g_A[BATCH * LAv * FILT];     // [b*LA+t][f]
__device__ float    g_T[BATCH * LQv * FILT];     // [b*LQ+q][g]
__device__ unsigned g_Bw[KCONV * FILT];          // conv weights [k'][f], tf32 bits, zero-padded
__device__ unsigned g_mq[BATCH * LQv];
__device__ unsigned g_ma[BATCH * LAv];

__device__ __forceinline__ unsigned enc_f(float f) {
    int i = __float_as_int(f);
    return (unsigned)(i ^ ((i >> 31) | 0x80000000));
}
__device__ __forceinline__ float dec_f(unsigned u) {
    int i = (u & 0x80000000u) ? (int)(u ^ 0x80000000u) : ~(int)u;
    return __int_as_float(i);
}
__device__ __forceinline__ unsigned f2tf(float f) {
    unsigned u;
    asm("cvt.rna.tf32.f32 %0, %1;" : "=r"(u) : "f"(f));
    return u;
}
__device__ __forceinline__ void mma8(float* c, const unsigned* a, const unsigned* b) {
    asm("mma.sync.aligned.m16n8k8.row.col.f32.tf32.tf32.f32 "
        "{%0,%1,%2,%3},{%4,%5,%6,%7},{%8,%9},{%0,%1,%2,%3};"
        : "+f"(c[0]), "+f"(c[1]), "+f"(c[2]), "+f"(c[3])
        : "r"(a[0]), "r"(a[1]), "r"(a[2]), "r"(a[3]), "r"(b[0]), "r"(b[1]));
}
__device__ __forceinline__ void cp16(void* sptr, const void* gptr, int bytes) {
    unsigned s = (unsigned)__cvta_generic_to_shared(sptr);
    asm volatile("cp.async.cg.shared.global [%0], [%1], 16, %2;"
                 :: "r"(s), "l"(gptr), "r"(bytes));
}
#define CP_COMMIT() asm volatile("cp.async.commit_group;")
#define CP_WAIT1()  asm volatile("cp.async.wait_group 1;")

// ---------------------------------------------------------------------------
// 0) init max buffers
// ---------------------------------------------------------------------------
__global__ void init_max_kernel() {
    int idx = blockIdx.x * blockDim.x + threadIdx.x;
    unsigned v = enc_f(-2.0f);
    if (idx < BATCH * LQv) g_mq[idx] = v;
    if (idx < BATCH * LAv) g_ma[idx] = v;
}

// ---------------------------------------------------------------------------
// 0b) pre-transpose conv weights: g_Bw[(koff*EPAD+e)*400 + f] = tf32(cw[f][e][koff])
// ---------------------------------------------------------------------------
__global__ void transpose_w_kernel(const float* __restrict__ cw) {
    int idx = blockIdx.x * blockDim.x + threadIdx.x;
    if (idx >= KCONV * FILT) return;
    int kp = idx / FILT, n = idx % FILT;
    int koff = kp / EPAD, e = kp % EPAD;
    float v = (e < EMBD) ? cw[(size_t)n * (EMBD * 3) + e * 3 + koff] : 0.0f;
    g_Bw[idx] = f2tf(v);
}

// ---------------------------------------------------------------------------
// 1) conv encode, tf32 mma, cp.async double-buffered, E-tile shared across koff.
//    Block tile: 128 tokens x 80 filters; 8 warps (4m x 2n), warp 32x40.
//    grid.x = 5: x==0 -> questions (L=128), x>=1 -> answers tile (x-1) (L=512).
//    Dynamic smem layout:
//      int   s_tok[136]
//      u32   E[2][130][36]   (rows 0..129 = tokens t0-1 .. t0+128; [m][k])
//      u32   B[2][3][32][88] ([koff][k][n])
// ---------------------------------------------------------------------------
#define C_KC 32
#define C_NCH (EPAD / C_KC)     // 10
#define E_PITCH 36
#define E_BUF  (130 * E_PITCH)  // 4680
#define B_PITCH 88
#define B_KOFF (C_KC * B_PITCH) // 2816
#define B_BUF  (3 * B_KOFF)     // 8448
#define SM_E_OFF 136
#define SM_B_OFF (SM_E_OFF + 2 * E_BUF)
#define SMEM_CONV ((SM_B_OFF + 2 * B_BUF) * 4)

__global__ __launch_bounds__(256, 2) void conv_encode_kernel(
    const int* __restrict__ qtok, const int* __restrict__ atok,
    const float* __restrict__ emb, const float* __restrict__ cb)
{
    extern __shared__ unsigned sm[];
    int*      s_tok = (int*)sm;
    unsigned* E     = sm + SM_E_OFF;
    unsigned* Bsm   = sm + SM_B_OFF;

    const int b   = blockIdx.z;
    const int n0  = blockIdx.y * 80;
    const int tid = threadIdx.x;
    const int wid = tid >> 5, lane = tid & 31;
    const int g   = lane >> 2, tig = lane & 3;
    const int wm  = wid & 3,  wn  = wid >> 2;
    const int mwb = wm * 32,  nwb = wn * 40;

    const int* tok;
    float* dst;
    int L, t0;
    if (blockIdx.x == 0) { tok = qtok; dst = g_Q; L = LQv; t0 = 0; }
    else                 { tok = atok; dst = g_A; L = LAv; t0 = (blockIdx.x - 1) * 128; }

    for (int r = tid; r < 130; r += 256) {
        int tg = t0 + r - 1;
        s_tok[r] = (tg >= 0 && tg < L) ? tok[b * L + tg] : 0;  // token 0 -> zero row
    }
    __syncthreads();

    // ---- prefetch one chunk into buffer bs ----
    auto prefetch = [&](int ch, int bs) {
        int ec = ch * C_KC;
        unsigned* Eb = E + bs * E_BUF;
        unsigned* Bb = Bsm + bs * B_BUF;
        for (int i = tid; i < 130 * 8; i += 256) {
            int r = i >> 3, sg = i & 7;
            int e = ec + sg * 4;
            int el = 300 - e; el = el < 0 ? 0 : (el > 4 ? 4 : el);
            int bytes = el * 4;
            const float* src = emb + (bytes ? ((size_t)s_tok[r] * EMBD + e) : 0);
            cp16(&Eb[r * E_PITCH + sg * 4], src, bytes);
        }
        for (int i = tid; i < 3 * C_KC * 20; i += 256) {
            int ko = i / 640; int r2 = i - ko * 640;
            int kc = r2 / 20; int sg = r2 - kc * 20;
            const unsigned* src = g_Bw + (size_t)(ko * EPAD + ec + kc) * FILT + n0 + sg * 4;
            cp16(&Bb[ko * B_KOFF + kc * B_PITCH + sg * 4], src, 16);
        }
    };

    float c[2][5][4];
#pragma unroll
    for (int i = 0; i < 2; i++)
#pragma unroll
        for (int j = 0; j < 5; j++)
#pragma unroll
            for (int k = 0; k < 4; k++) c[i][j][k] = 0.0f;

    prefetch(0, 0);
    CP_COMMIT();

    for (int ch = 0; ch < C_NCH; ch++) {
        int bs = ch & 1;
        if (ch + 1 < C_NCH) prefetch(ch + 1, bs ^ 1);
        CP_COMMIT();
        CP_WAIT1();
        __syncthreads();

        const unsigned* Eb = E + bs * E_BUF;
        const unsigned* Bb = Bsm + bs * B_BUF;

#pragma unroll
        for (int ko = 0; ko < 3; ko++) {
#pragma unroll
            for (int kb = 0; kb < C_KC / 8; kb++) {
                int kk = kb * 8;
                unsigned a[2][4];
#pragma unroll
                for (int ms = 0; ms < 2; ms++) {
                    int row = mwb + ms * 16 + g + ko;
                    a[ms][0] = Eb[(row)     * E_PITCH + kk + tig];
                    a[ms][1] = Eb[(row + 8) * E_PITCH + kk + tig];
                    a[ms][2] = Eb[(row)     * E_PITCH + kk + tig + 4];
                    a[ms][3] = Eb[(row + 8) * E_PITCH + kk + tig + 4];
                }
                const unsigned* Bk = Bb + ko * B_KOFF;
#pragma unroll
                for (int ns = 0; ns < 5; ns++) {
                    unsigned bf[2];
                    int nb = nwb + ns * 8 + g;
                    bf[0] = Bk[(kk + tig)     * B_PITCH + nb];
                    bf[1] = Bk[(kk + tig + 4) * B_PITCH + nb];
                    mma8(c[0][ns], a[0], bf);
                    mma8(c[1][ns], a[1], bf);
                }
            }
        }
        __syncthreads();
    }

    // epilogue: + bias, store
#pragma unroll
    for (int ms = 0; ms < 2; ms++) {
#pragma unroll
        for (int ns = 0; ns < 5; ns++) {
            int col = n0 + nwb + ns * 8 + 2 * tig;
            float2 bias = *(const float2*)&cb[col];
            int row0 = t0 + mwb + ms * 16 + g;
            *(float2*)&dst[((size_t)b * L + row0) * FILT + col] =
                make_float2(c[ms][ns][0] + bias.x, c[ms][ns][1] + bias.y);
            *(float2*)&dst[((size_t)b * L + row0 + 8) * FILT + col] =
                make_float2(c[ms][ns][2] + bias.x, c[ms][ns][3] + bias.y);
        }
    }
}

// ---------------------------------------------------------------------------
// 2) T = Qm @ W : M=128, N=400 (5 x 80), K=400. KC=40.
// ---------------------------------------------------------------------------
#define T_KC 40
#define T_AP 136
#define T_BP 88

__global__ __launch_bounds__(256) void gemm_T_kernel(const float* __restrict__ W)
{
    __shared__ unsigned As[T_KC][T_AP];
    __shared__ unsigned Bs[T_KC][T_BP];

    const int b  = blockIdx.z;
    const int n0 = blockIdx.x * 80;
    const int tid  = threadIdx.x;
    const int wid  = tid >> 5, lane = tid & 31;
    const int g    = lane >> 2, tig = lane & 3;
    const int wm   = wid & 3,  wn  = wid >> 2;
    const int mwb  = wm * 32, nwb = wn * 40;

    float c[2][5][4];
#pragma unroll
    for (int i = 0; i < 2; i++)
#pragma unroll
        for (int j = 0; j < 5; j++)
#pragma unroll
            for (int k = 0; k < 4; k++) c[i][j][k] = 0.0f;

    for (int k0 = 0; k0 < FILT; k0 += T_KC) {
#pragma unroll
        for (int it = 0; it < 5; it++) {
            int i = tid + it * 256;
            int m = i / 10, k4 = i - m * 10;
            float4 v = *(const float4*)&g_Q[((size_t)b * LQv + m) * FILT + k0 + k4 * 4];
            As[k4 * 4 + 0][m] = f2tf(v.x);
            As[k4 * 4 + 1][m] = f2tf(v.y);
            As[k4 * 4 + 2][m] = f2tf(v.z);
            As[k4 * 4 + 3][m] = f2tf(v.w);
        }
        for (int i = tid; i < T_KC * 80; i += 256) {
            int kc = i / 80, n = i - kc * 80;
            Bs[kc][n] = f2tf(W[(size_t)(k0 + kc) * FILT + n0 + n]);
        }
        __syncthreads();

#pragma unroll
        for (int kb = 0; kb < T_KC / 8; kb++) {
            int kk = kb * 8;
            unsigned a[2][4];
#pragma unroll
            for (int ms = 0; ms < 2; ms++) {
                int rb = mwb + ms * 16 + g;
                a[ms][0] = As[kk + tig][rb];
                a[ms][1] = As[kk + tig][rb + 8];
                a[ms][2] = As[kk + tig + 4][rb];
                a[ms][3] = As[kk + tig + 4][rb + 8];
            }
#pragma unroll
            for (int ns = 0; ns < 5; ns++) {
                unsigned bf[2];
                int nb = nwb + ns * 8 + g;
                bf[0] = Bs[kk + tig][nb];
                bf[1] = Bs[kk + tig + 4][nb];
                mma8(c[0][ns], a[0], bf);
                mma8(c[1][ns], a[1], bf);
            }
        }
        __syncthreads();
    }

#pragma unroll
    for (int ms = 0; ms < 2; ms++) {
#pragma unroll
        for (int ns = 0; ns < 5; ns++) {
            int col = n0 + nwb + ns * 8 + 2 * tig;
            int row0 = mwb + ms * 16 + g;
            *(float2*)&g_T[((size_t)b * LQv + row0) * FILT + col] =
                make_float2(c[ms][ns][0], c[ms][ns][1]);
            *(float2*)&g_T[((size_t)b * LQv + row0 + 8) * FILT + col] =
                make_float2(c[ms][ns][2], c[ms][ns][3]);
        }
    }
}

// ---------------------------------------------------------------------------
// 3) G = tanh(T @ A^T) fused row/col max. M=128(q), N=512 (8 x 64), K=400.
// ---------------------------------------------------------------------------
#define G_KC 40
#define G_AP 136
#define G_BP 72

__global__ __launch_bounds__(256) void gemm_G_kernel()
{
    __shared__ unsigned As[G_KC][G_AP];
    __shared__ unsigned Bs[G_KC][G_BP];
    __shared__ unsigned srow[128], scol[64];

    const int b  = blockIdx.z;
    const int a0 = blockIdx.x * 64;
    const int tid  = threadIdx.x;
    const int wid  = tid >> 5, lane = tid & 31;
    const int g    = lane >> 2, tig = lane & 3;
    const int wm   = wid & 3,  wn  = wid >> 2;
    const int mwb  = wm * 32, nwb = wn * 32;

    if (tid < 128) srow[tid] = enc_f(-2.0f);
    if (tid < 64)  scol[tid] = enc_f(-2.0f);

    float c[2][4][4];
#pragma unroll
    for (int i = 0; i < 2; i++)
#pragma unroll
        for (int j = 0; j < 4; j++)
#pragma unroll
            for (int k = 0; k < 4; k++) c[i][j][k] = 0.0f;

    for (int k0 = 0; k0 < FILT; k0 += G_KC) {
        __syncthreads();
#pragma unroll
        for (int it = 0; it < 5; it++) {
            int i = tid + it * 256;
            int m = i / 10, k4 = i - m * 10;
            float4 v = *(const float4*)&g_T[((size_t)b * LQv + m) * FILT + k0 + k4 * 4];
            As[k4 * 4 + 0][m] = f2tf(v.x);
            As[k4 * 4 + 1][m] = f2tf(v.y);
            As[k4 * 4 + 2][m] = f2tf(v.z);
            As[k4 * 4 + 3][m] = f2tf(v.w);
        }
        for (int i = tid; i < 640; i += 256) {
            int n = i / 10, k4 = i - n * 10;
            float4 v = *(const float4*)&g_A[((size_t)b * LAv + a0 + n) * FILT + k0 + k4 * 4];
            Bs[k4 * 4 + 0][n] = f2tf(v.x);
            Bs[k4 * 4 + 1][n] = f2tf(v.y);
            Bs[k4 * 4 + 2][n] = f2tf(v.z);
            Bs[k4 * 4 + 3][n] = f2tf(v.w);
        }
        __syncthreads();

#pragma unroll
        for (int kb = 0; kb < G_KC / 8; kb++) {
            int kk = kb * 8;
            unsigned a[2][4];
#pragma unroll
            for (int ms = 0; ms < 2; ms++) {
                int rb = mwb + ms * 16 + g;
                a[ms][0] = As[kk + tig][rb];
                a[ms][1] = As[kk + tig][rb + 8];
                a[ms][2] = As[kk + tig + 4][rb];
                a[ms][3] = As[kk + tig + 4][rb + 8];
            }
#pragma unroll
            for (int ns = 0; ns < 4; ns++) {
                unsigned bf[2];
                int nb = nwb + ns * 8 + g;
                bf[0] = Bs[kk + tig][nb];
                bf[1] = Bs[kk + tig + 4][nb];
                mma8(c[0][ns], a[0], bf);
                mma8(c[1][ns], a[1], bf);
            }
        }
    }
    __syncthreads();

    float tv[2][4][4];
#pragma unroll
    for (int ms = 0; ms < 2; ms++)
#pragma unroll
        for (int ns = 0; ns < 4; ns++)
#pragma unroll
            for (int k = 0; k < 4; k++) tv[ms][ns][k] = tanhf(c[ms][ns][k]);

#pragma unroll
    for (int ms = 0; ms < 2; ms++) {
        float r0 = -2.0f, r1 = -2.0f;
#pragma unroll
        for (int ns = 0; ns < 4; ns++) {
            r0 = fmaxf(r0, fmaxf(tv[ms][ns][0], tv[ms][ns][1]));
            r1 = fmaxf(r1, fmaxf(tv[ms][ns][2], tv[ms][ns][3]));
        }
        atomicMax(&srow[mwb + ms * 16 + g],     enc_f(r0));
        atomicMax(&srow[mwb + ms * 16 + g + 8], enc_f(r1));
    }
#pragma unroll
    for (int ns = 0; ns < 4; ns++) {
        float c0 = -2.0f, c1 = -2.0f;
#pragma unroll
        for (int ms = 0; ms < 2; ms++) {
            c0 = fmaxf(c0, fmaxf(tv[ms][ns][0], tv[ms][ns][2]));
            c1 = fmaxf(c1, fmaxf(tv[ms][ns][1], tv[ms][ns][3]));
        }
        int nb = nwb + ns * 8 + 2 * tig;
        atomicMax(&scol[nb],     enc_f(c0));
        atomicMax(&scol[nb + 1], enc_f(c1));
    }
    __syncthreads();

    if (tid < 128) atomicMax(&g_mq[b * LQv + tid], srow[tid]);
    if (tid < 64)  atomicMax(&g_ma[b * LAv + a0 + tid], scol[tid]);
}

// ---------------------------------------------------------------------------
// 4) per-batch finalize (softmax over maxes, pooling, cosine)
// ---------------------------------------------------------------------------
__global__ __launch_bounds__(256) void finalize_kernel(float* __restrict__ out)
{
    __shared__ float sq[LQv], sa[LAv], rq[FILT], ra[FILT];
    __shared__ float smax[2], ssum[2];
    __shared__ float sd[256], sx[256], sy[256];

    const int b = blockIdx.x;
    const int tid = threadIdx.x;

    for (int q = tid; q < LQv; q += 256) sq[q] = dec_f(g_mq[b * LQv + q]);
    for (int a = tid; a < LAv; a += 256) sa[a] = dec_f(g_ma[b * LAv + a]);
    __syncthreads();

    if (tid == 0) {
        float m = -1e30f;
        for (int q = 0; q < LQv; q++) m = fmaxf(m, sq[q]);
        smax[0] = m;
    } else if (tid == 32) {
        float m = -1e30f;
        for (int a = 0; a < LAv; a++) m = fmaxf(m, sa[a]);
        smax[1] = m;
    }
    __syncthreads();
    for (int q = tid; q < LQv; q += 256) sq[q] = expf(sq[q] - smax[0]);
    for (int a = tid; a < LAv; a += 256) sa[a] = expf(sa[a] - smax[1]);
    __syncthreads();
    if (tid == 0) {
        float s = 0.0f;
        for (int q = 0; q < LQv; q++) s += sq[q];
        ssum[0] = s;
    } else if (tid == 32) {
        float s = 0.0f;
        for (int a = 0; a < LAv; a++) s += sa[a];
        ssum[1] = s;
    }
    __syncthreads();
    {
        float invq = 1.0f / ssum[0], inva = 1.0f / ssum[1];
        for (int q = tid; q < LQv; q += 256) sq[q] *= invq;
        for (int a = tid; a < LAv; a += 256) sa[a] *= inva;
    }
    __syncthreads();

    for (int f = tid; f < FILT; f += 256) {
        const float* qp = g_Q + (size_t)b * LQv * FILT + f;
        float acc = 0.0f;
        for (int q = 0; q < LQv; q++) acc += qp[(size_t)q * FILT] * sq[q];
        rq[f] = acc;
    }
    for (int f = tid; f < FILT; f += 256) {
        const float* ap = g_A + (size_t)b * LAv * FILT + f;
        float acc = 0.0f;
        for (int a = 0; a < LAv; a++) acc += ap[(size_t)a * FILT] * sa[a];
        ra[f] = acc;
    }
    __syncthreads();

    float d = 0.0f, x = 0.0f, y = 0.0f;
    for (int f = tid; f < FILT; f += 256) {
        d += rq[f] * ra[f];
        x += rq[f] * rq[f];
        y += ra[f] * ra[f];
    }
    sd[tid] = d; sx[tid] = x; sy[tid] = y;
    __syncthreads();
    if (tid == 0) {
        float D = 0.0f, X = 0.0f, Y = 0.0f;
        for (int i = 0; i < 256; i++) { D += sd[i]; X += sx[i]; Y += sy[i]; }
        float nq = fmaxf(sqrtf(X), 1e-8f);
        float na = fmaxf(sqrtf(Y), 1e-8f);
        out[b] = D / (nq * na);
    }
}

// ---------------------------------------------------------------------------
// launch
// ---------------------------------------------------------------------------
extern "C" void kernel_launch(void* const* d_in, const int* in_sizes, int n_in,
                              void* d_out, int out_size)
{
    const int*   questions = (const int*)d_in[0];
    const int*   answers   = (const int*)d_in[1];
    const float* emb       = (const float*)d_in[2];
    const float* conv_w    = (const float*)d_in[3];
    const float* conv_b    = (const float*)d_in[4];
    const float* W         = (const float*)d_in[5];
    float*       out       = (float*)d_out;

    (void)in_sizes; (void)n_in; (void)out_size;

    static bool attr_done = false;
    if (!attr_done) {
        cudaFuncSetAttribute(conv_encode_kernel,
                             cudaFuncAttributeMaxDynamicSharedMemorySize, SMEM_CONV);
        attr_done = true;
    }

    init_max_kernel<<<(BATCH * LAv + 255) / 256, 256>>>();
    transpose_w_kernel<<<(KCONV * FILT + 255) / 256, 256>>>(conv_w);

    conv_encode_kernel<<<dim3(5, FILT / 80, BATCH), 256, SMEM_CONV>>>(
        questions, answers, emb, conv_b);

    gemm_T_kernel<<<dim3(FILT / 80, 1, BATCH), 256>>>(W);
    gemm_G_kernel<<<dim3(LAv / 64, 1, BATCH), 256>>>();

    finalize_kernel<<<BATCH, 256>>>(out);
}

// round 5
// speedup vs baseline: 6.5337x; 1.3194x over previous
#include <cuda_runtime.h>
#include <math.h>

#define BATCH 128
#define LQv   128
#define LAv   512
#define EMBD  300
#define FILT  400
#define EPAD  320
#define KCONV (3 * EPAD)   // 960

// ---- scratch (static __device__: no allocations allowed) ----
__device__ float    g_Q[BATCH * LQv * FILT];     // [b*LQ+t][f]
__device__ float    g_A[BATCH * LAv * FILT];     // [b*LA+t][f]
__device__ float    g_T[BATCH * LQv * FILT];     // [b*LQ+q][g]
__device__ unsigned g_Bw[KCONV * FILT];          // conv weights [k'][f], tf32 bits, zero-padded
__device__ unsigned g_mq[BATCH * LQv];
__device__ unsigned g_ma[BATCH * LAv];

__device__ __forceinline__ unsigned enc_f(float f) {
    int i = __float_as_int(f);
    return (unsigned)(i ^ ((i >> 31) | 0x80000000));
}
__device__ __forceinline__ float dec_f(unsigned u) {
    int i = (u & 0x80000000u) ? (int)(u ^ 0x80000000u) : ~(int)u;
    return __int_as_float(i);
}
__device__ __forceinline__ unsigned f2tf(float f) {
    unsigned u;
    asm("cvt.rna.tf32.f32 %0, %1;" : "=r"(u) : "f"(f));
    return u;
}
__device__ __forceinline__ void mma8(float* c, const unsigned* a, const unsigned* b) {
    asm("mma.sync.aligned.m16n8k8.row.col.f32.tf32.tf32.f32 "
        "{%0,%1,%2,%3},{%4,%5,%6,%7},{%8,%9},{%0,%1,%2,%3};"
        : "+f"(c[0]), "+f"(c[1]), "+f"(c[2]), "+f"(c[3])
        : "r"(a[0]), "r"(a[1]), "r"(a[2]), "r"(a[3]), "r"(b[0]), "r"(b[1]));
}
__device__ __forceinline__ void cp16(void* sptr, const void* gptr, int bytes) {
    unsigned s = (unsigned)__cvta_generic_to_shared(sptr);
    asm volatile("cp.async.cg.shared.global [%0], [%1], 16, %2;"
                 :: "r"(s), "l"(gptr), "r"(bytes));
}
__device__ __forceinline__ void cp16f(void* sptr, const void* gptr) {
    unsigned s = (unsigned)__cvta_generic_to_shared(sptr);
    asm volatile("cp.async.cg.shared.global [%0], [%1], 16;"
                 :: "r"(s), "l"(gptr));
}
#define CP_COMMIT() asm volatile("cp.async.commit_group;")
#define CP_WAIT1()  asm volatile("cp.async.wait_group 1;")

// ---------------------------------------------------------------------------
// 0) init max buffers
// ---------------------------------------------------------------------------
__global__ void init_max_kernel() {
    int idx = blockIdx.x * blockDim.x + threadIdx.x;
    unsigned v = enc_f(-2.0f);
    if (idx < BATCH * LQv) g_mq[idx] = v;
    if (idx < BATCH * LAv) g_ma[idx] = v;
}

// ---------------------------------------------------------------------------
// 0b) pre-transpose conv weights
// ---------------------------------------------------------------------------
__global__ void transpose_w_kernel(const float* __restrict__ cw) {
    int idx = blockIdx.x * blockDim.x + threadIdx.x;
    if (idx >= KCONV * FILT) return;
    int kp = idx / FILT, n = idx % FILT;
    int koff = kp / EPAD, e = kp % EPAD;
    float v = (e < EMBD) ? cw[(size_t)n * (EMBD * 3) + e * 3 + koff] : 0.0f;
    g_Bw[idx] = f2tf(v);
}

// ---------------------------------------------------------------------------
// 1) conv encode, tf32 mma, cp.async double-buffered (unchanged from R3)
// ---------------------------------------------------------------------------
#define C_KC 32
#define C_NCH (EPAD / C_KC)     // 10
#define E_PITCH 36
#define E_BUF  (130 * E_PITCH)
#define B_PITCH 88
#define B_KOFF (C_KC * B_PITCH)
#define B_BUF  (3 * B_KOFF)
#define SM_E_OFF 136
#define SM_B_OFF (SM_E_OFF + 2 * E_BUF)
#define SMEM_CONV ((SM_B_OFF + 2 * B_BUF) * 4)

__global__ __launch_bounds__(256, 2) void conv_encode_kernel(
    const int* __restrict__ qtok, const int* __restrict__ atok,
    const float* __restrict__ emb, const float* __restrict__ cb)
{
    extern __shared__ unsigned sm[];
    int*      s_tok = (int*)sm;
    unsigned* E     = sm + SM_E_OFF;
    unsigned* Bsm   = sm + SM_B_OFF;

    const int b   = blockIdx.z;
    const int n0  = blockIdx.y * 80;
    const int tid = threadIdx.x;
    const int wid = tid >> 5, lane = tid & 31;
    const int g   = lane >> 2, tig = lane & 3;
    const int wm  = wid & 3,  wn  = wid >> 2;
    const int mwb = wm * 32,  nwb = wn * 40;

    const int* tok;
    float* dst;
    int L, t0;
    if (blockIdx.x == 0) { tok = qtok; dst = g_Q; L = LQv; t0 = 0; }
    else                 { tok = atok; dst = g_A; L = LAv; t0 = (blockIdx.x - 1) * 128; }

    for (int r = tid; r < 130; r += 256) {
        int tg = t0 + r - 1;
        s_tok[r] = (tg >= 0 && tg < L) ? tok[b * L + tg] : 0;
    }
    __syncthreads();

    auto prefetch = [&](int ch, int bs) {
        int ec = ch * C_KC;
        unsigned* Eb = E + bs * E_BUF;
        unsigned* Bb = Bsm + bs * B_BUF;
        for (int i = tid; i < 130 * 8; i += 256) {
            int r = i >> 3, sg = i & 7;
            int e = ec + sg * 4;
            int el = 300 - e; el = el < 0 ? 0 : (el > 4 ? 4 : el);
            int bytes = el * 4;
            const float* src = emb + (bytes ? ((size_t)s_tok[r] * EMBD + e) : 0);
            cp16(&Eb[r * E_PITCH + sg * 4], src, bytes);
        }
        for (int i = tid; i < 3 * C_KC * 20; i += 256) {
            int ko = i / 640; int r2 = i - ko * 640;
            int kc = r2 / 20; int sg = r2 - kc * 20;
            const unsigned* src = g_Bw + (size_t)(ko * EPAD + ec + kc) * FILT + n0 + sg * 4;
            cp16f(&Bb[ko * B_KOFF + kc * B_PITCH + sg * 4], src);
        }
    };

    float c[2][5][4];
#pragma unroll
    for (int i = 0; i < 2; i++)
#pragma unroll
        for (int j = 0; j < 5; j++)
#pragma unroll
            for (int k = 0; k < 4; k++) c[i][j][k] = 0.0f;

    prefetch(0, 0);
    CP_COMMIT();

    for (int ch = 0; ch < C_NCH; ch++) {
        int bs = ch & 1;
        if (ch + 1 < C_NCH) prefetch(ch + 1, bs ^ 1);
        CP_COMMIT();
        CP_WAIT1();
        __syncthreads();

        const unsigned* Eb = E + bs * E_BUF;
        const unsigned* Bb = Bsm + bs * B_BUF;

#pragma unroll
        for (int ko = 0; ko < 3; ko++) {
#pragma unroll
            for (int kb = 0; kb < C_KC / 8; kb++) {
                int kk = kb * 8;
                unsigned a[2][4];
#pragma unroll
                for (int ms = 0; ms < 2; ms++) {
                    int row = mwb + ms * 16 + g + ko;
                    a[ms][0] = Eb[(row)     * E_PITCH + kk + tig];
                    a[ms][1] = Eb[(row + 8) * E_PITCH + kk + tig];
                    a[ms][2] = Eb[(row)     * E_PITCH + kk + tig + 4];
                    a[ms][3] = Eb[(row + 8) * E_PITCH + kk + tig + 4];
                }
                const unsigned* Bk = Bb + ko * B_KOFF;
#pragma unroll
                for (int ns = 0; ns < 5; ns++) {
                    unsigned bf[2];
                    int nb = nwb + ns * 8 + g;
                    bf[0] = Bk[(kk + tig)     * B_PITCH + nb];
                    bf[1] = Bk[(kk + tig + 4) * B_PITCH + nb];
                    mma8(c[0][ns], a[0], bf);
                    mma8(c[1][ns], a[1], bf);
                }
            }
        }
        __syncthreads();
    }

#pragma unroll
    for (int ms = 0; ms < 2; ms++) {
#pragma unroll
        for (int ns = 0; ns < 5; ns++) {
            int col = n0 + nwb + ns * 8 + 2 * tig;
            float2 bias = *(const float2*)&cb[col];
            int row0 = t0 + mwb + ms * 16 + g;
            *(float2*)&dst[((size_t)b * L + row0) * FILT + col] =
                make_float2(c[ms][ns][0] + bias.x, c[ms][ns][1] + bias.y);
            *(float2*)&dst[((size_t)b * L + row0 + 8) * FILT + col] =
                make_float2(c[ms][ns][2] + bias.x, c[ms][ns][3] + bias.y);
        }
    }
}

// ---------------------------------------------------------------------------
// 2) T = Qm @ W : M=128, N=400 (5 x 80), K=400. cp.async 2-stage, no cvt.
//    Smem: A [m][k] pitch 44, B [k][n] pitch 88.
// ---------------------------------------------------------------------------
#define T_KC 40
#define T_AP 44
#define T_BP 88
#define T_ABUF (128 * T_AP)          // 5632 u32
#define T_BOFF (2 * T_ABUF)          // 11264
#define T_BBUF (T_KC * T_BP)         // 3520
#define SMEM_T ((T_BOFF + 2 * T_BBUF) * 4)   // 73216 B

__global__ __launch_bounds__(256, 2) void gemm_T_kernel(const float* __restrict__ W)
{
    extern __shared__ unsigned sm[];
    unsigned* Asm = sm;
    unsigned* Bsm = sm + T_BOFF;

    const int b  = blockIdx.z;
    const int n0 = blockIdx.x * 80;
    const int tid  = threadIdx.x;
    const int wid  = tid >> 5, lane = tid & 31;
    const int g    = lane >> 2, tig = lane & 3;
    const int wm   = wid & 3,  wn  = wid >> 2;
    const int mwb  = wm * 32, nwb = wn * 40;

    const float* Qb = g_Q + (size_t)b * LQv * FILT;

    auto prefetch = [&](int ch, int bs) {
        int k0 = ch * T_KC;
        unsigned* Ab = Asm + bs * T_ABUF;
        unsigned* Bb = Bsm + bs * T_BBUF;
#pragma unroll
        for (int it = 0; it < 5; it++) {
            int i = tid + it * 256;                 // 1280 = 128 m x 10 k4
            int m = i / 10, k4 = i - m * 10;
            cp16f(&Ab[m * T_AP + k4 * 4], Qb + (size_t)m * FILT + k0 + k4 * 4);
        }
        for (int i = tid; i < T_KC * 20; i += 256) { // 800 = 40 k x 20 n4
            int kc = i / 20, sg = i - kc * 20;
            cp16f(&Bb[kc * T_BP + sg * 4], W + (size_t)(k0 + kc) * FILT + n0 + sg * 4);
        }
    };

    float c[2][5][4];
#pragma unroll
    for (int i = 0; i < 2; i++)
#pragma unroll
        for (int j = 0; j < 5; j++)
#pragma unroll
            for (int k = 0; k < 4; k++) c[i][j][k] = 0.0f;

    prefetch(0, 0);
    CP_COMMIT();

    for (int ch = 0; ch < FILT / T_KC; ch++) {
        int bs = ch & 1;
        if (ch + 1 < FILT / T_KC) prefetch(ch + 1, bs ^ 1);
        CP_COMMIT();
        CP_WAIT1();
        __syncthreads();

        const unsigned* Ab = Asm + bs * T_ABUF;
        const unsigned* Bb = Bsm + bs * T_BBUF;

#pragma unroll
        for (int kb = 0; kb < T_KC / 8; kb++) {
            int kk = kb * 8;
            unsigned a[2][4];
#pragma unroll
            for (int ms = 0; ms < 2; ms++) {
                int row = mwb + ms * 16 + g;
                a[ms][0] = Ab[(row)     * T_AP + kk + tig];
                a[ms][1] = Ab[(row + 8) * T_AP + kk + tig];
                a[ms][2] = Ab[(row)     * T_AP + kk + tig + 4];
                a[ms][3] = Ab[(row + 8) * T_AP + kk + tig + 4];
            }
#pragma unroll
            for (int ns = 0; ns < 5; ns++) {
                unsigned bf[2];
                int nb = nwb + ns * 8 + g;
                bf[0] = Bb[(kk + tig)     * T_BP + nb];
                bf[1] = Bb[(kk + tig + 4) * T_BP + nb];
                mma8(c[0][ns], a[0], bf);
                mma8(c[1][ns], a[1], bf);
            }
        }
        __syncthreads();
    }

#pragma unroll
    for (int ms = 0; ms < 2; ms++) {
#pragma unroll
        for (int ns = 0; ns < 5; ns++) {
            int col = n0 + nwb + ns * 8 + 2 * tig;
            int row0 = mwb + ms * 16 + g;
            *(float2*)&g_T[((size_t)b * LQv + row0) * FILT + col] =
                make_float2(c[ms][ns][0], c[ms][ns][1]);
            *(float2*)&g_T[((size_t)b * LQv + row0 + 8) * FILT + col] =
                make_float2(c[ms][ns][2], c[ms][ns][3]);
        }
    }
}

// ---------------------------------------------------------------------------
// 3) G = tanh(T @ A^T) fused row/col max. M=128, N=512 (8 x 64), K=400.
//    cp.async 2-stage, no cvt. Smem: A [q][k] pitch 44, B [a][k] pitch 44.
// ---------------------------------------------------------------------------
#define G_KC 40
#define G_AP 44
#define G_ABUF (128 * G_AP)          // 5632
#define G_BOFF (2 * G_ABUF)          // 11264
#define G_BBUF (64 * G_AP)           // 2816
#define G_RED  (G_BOFF + 2 * G_BBUF) // 16896 (srow/scol live after buffers)
#define SMEM_G ((G_RED + 192) * 4)

__global__ __launch_bounds__(256, 2) void gemm_G_kernel()
{
    extern __shared__ unsigned sm[];
    unsigned* Asm  = sm;
    unsigned* Bsm  = sm + G_BOFF;
    unsigned* srow = sm + G_RED;        // 128
    unsigned* scol = sm + G_RED + 128;  // 64

    const int b  = blockIdx.z;
    const int a0 = blockIdx.x * 64;
    const int tid  = threadIdx.x;
    const int wid  = tid >> 5, lane = tid & 31;
    const int g    = lane >> 2, tig = lane & 3;
    const int wm   = wid & 3,  wn  = wid >> 2;
    const int mwb  = wm * 32, nwb = wn * 32;

    if (tid < 128) srow[tid] = enc_f(-2.0f);
    if (tid < 64)  scol[tid] = enc_f(-2.0f);

    const float* Tb = g_T + (size_t)b * LQv * FILT;
    const float* Ab0 = g_A + ((size_t)b * LAv + a0) * FILT;

    auto prefetch = [&](int ch, int bs) {
        int k0 = ch * G_KC;
        unsigned* Abuf = Asm + bs * G_ABUF;
        unsigned* Bbuf = Bsm + bs * G_BBUF;
#pragma unroll
        for (int it = 0; it < 5; it++) {
            int i = tid + it * 256;                  // 1280 = 128 q x 10 k4
            int m = i / 10, k4 = i - m * 10;
            cp16f(&Abuf[m * G_AP + k4 * 4], Tb + (size_t)m * FILT + k0 + k4 * 4);
        }
        for (int i = tid; i < 640; i += 256) {       // 64 a x 10 k4
            int n = i / 10, k4 = i - n * 10;
            cp16f(&Bbuf[n * G_AP + k4 * 4], Ab0 + (size_t)n * FILT + k0 + k4 * 4);
        }
    };

    float c[2][4][4];
#pragma unroll
    for (int i = 0; i < 2; i++)
#pragma unroll
        for (int j = 0; j < 4; j++)
#pragma unroll
            for (int k = 0; k < 4; k++) c[i][j][k] = 0.0f;

    prefetch(0, 0);
    CP_COMMIT();

    for (int ch = 0; ch < FILT / G_KC; ch++) {
        int bs = ch & 1;
        if (ch + 1 < FILT / G_KC) prefetch(ch + 1, bs ^ 1);
        CP_COMMIT();
        CP_WAIT1();
        __syncthreads();

        const unsigned* Abuf = Asm + bs * G_ABUF;
        const unsigned* Bbuf = Bsm + bs * G_BBUF;

#pragma unroll
        for (int kb = 0; kb < G_KC / 8; kb++) {
            int kk = kb * 8;
            unsigned a[2][4];
#pragma unroll
            for (int ms = 0; ms < 2; ms++) {
                int row = mwb + ms * 16 + g;
                a[ms][0] = Abuf[(row)     * G_AP + kk + tig];
                a[ms][1] = Abuf[(row + 8) * G_AP + kk + tig];
                a[ms][2] = Abuf[(row)     * G_AP + kk + tig + 4];
                a[ms][3] = Abuf[(row + 8) * G_AP + kk + tig + 4];
            }
#pragma unroll
            for (int ns = 0; ns < 4; ns++) {
                unsigned bf[2];
                int nb = nwb + ns * 8 + g;
                bf[0] = Bbuf[nb * G_AP + kk + tig];
                bf[1] = Bbuf[nb * G_AP + kk + tig + 4];
                mma8(c[0][ns], a[0], bf);
                mma8(c[1][ns], a[1], bf);
            }
        }
        __syncthreads();
    }

    float tv[2][4][4];
#pragma unroll
    for (int ms = 0; ms < 2; ms++)
#pragma unroll
        for (int ns = 0; ns < 4; ns++)
#pragma unroll
            for (int k = 0; k < 4; k++) tv[ms][ns][k] = tanhf(c[ms][ns][k]);

#pragma unroll
    for (int ms = 0; ms < 2; ms++) {
        float r0 = -2.0f, r1 = -2.0f;
#pragma unroll
        for (int ns = 0; ns < 4; ns++) {
            r0 = fmaxf(r0, fmaxf(tv[ms][ns][0], tv[ms][ns][1]));
            r1 = fmaxf(r1, fmaxf(tv[ms][ns][2], tv[ms][ns][3]));
        }
        atomicMax(&srow[mwb + ms * 16 + g],     enc_f(r0));
        atomicMax(&srow[mwb + ms * 16 + g + 8], enc_f(r1));
    }
#pragma unroll
    for (int ns = 0; ns < 4; ns++) {
        float c0 = -2.0f, c1 = -2.0f;
#pragma unroll
        for (int ms = 0; ms < 2; ms++) {
            c0 = fmaxf(c0, fmaxf(tv[ms][ns][0], tv[ms][ns][2]));
            c1 = fmaxf(c1, fmaxf(tv[ms][ns][1], tv[ms][ns][3]));
        }
        int nb = nwb + ns * 8 + 2 * tig;
        atomicMax(&scol[nb],     enc_f(c0));
        atomicMax(&scol[nb + 1], enc_f(c1));
    }
    __syncthreads();

    if (tid < 128) atomicMax(&g_mq[b * LQv + tid], srow[tid]);
    if (tid < 64)  atomicMax(&g_ma[b * LAv + a0 + tid], scol[tid]);
}

// ---------------------------------------------------------------------------
// 4) per-batch finalize (softmax over maxes, pooling, cosine)
// ---------------------------------------------------------------------------
__global__ __launch_bounds__(256) void finalize_kernel(float* __restrict__ out)
{
    __shared__ float sq[LQv], sa[LAv], rq[FILT], ra[FILT];
    __shared__ float smax[2], ssum[2];
    __shared__ float sd[256], sx[256], sy[256];

    const int b = blockIdx.x;
    const int tid = threadIdx.x;

    for (int q = tid; q < LQv; q += 256) sq[q] = dec_f(g_mq[b * LQv + q]);
    for (int a = tid; a < LAv; a += 256) sa[a] = dec_f(g_ma[b * LAv + a]);
    __syncthreads();

    if (tid == 0) {
        float m = -1e30f;
        for (int q = 0; q < LQv; q++) m = fmaxf(m, sq[q]);
        smax[0] = m;
    } else if (tid == 32) {
        float m = -1e30f;
        for (int a = 0; a < LAv; a++) m = fmaxf(m, sa[a]);
        smax[1] = m;
    }
    __syncthreads();
    for (int q = tid; q < LQv; q += 256) sq[q] = expf(sq[q] - smax[0]);
    for (int a = tid; a < LAv; a += 256) sa[a] = expf(sa[a] - smax[1]);
    __syncthreads();
    if (tid == 0) {
        float s = 0.0f;
        for (int q = 0; q < LQv; q++) s += sq[q];
        ssum[0] = s;
    } else if (tid == 32) {
        float s = 0.0f;
        for (int a = 0; a < LAv; a++) s += sa[a];
        ssum[1] = s;
    }
    __syncthreads();
    {
        float invq = 1.0f / ssum[0], inva = 1.0f / ssum[1];
        for (int q = tid; q < LQv; q += 256) sq[q] *= invq;
        for (int a = tid; a < LAv; a += 256) sa[a] *= inva;
    }
    __syncthreads();

    for (int f = tid; f < FILT; f += 256) {
        const float* qp = g_Q + (size_t)b * LQv * FILT + f;
        float acc = 0.0f;
        for (int q = 0; q < LQv; q++) acc += qp[(size_t)q * FILT] * sq[q];
        rq[f] = acc;
    }
    for (int f = tid; f < FILT; f += 256) {
        const float* ap = g_A + (size_t)b * LAv * FILT + f;
        float acc = 0.0f;
        for (int a = 0; a < LAv; a++) acc += ap[(size_t)a * FILT] * sa[a];
        ra[f] = acc;
    }
    __syncthreads();

    float d = 0.0f, x = 0.0f, y = 0.0f;
    for (int f = tid; f < FILT; f += 256) {
        d += rq[f] * ra[f];
        x += rq[f] * rq[f];
        y += ra[f] * ra[f];
    }
    sd[tid] = d; sx[tid] = x; sy[tid] = y;
    __syncthreads();
    if (tid == 0) {
        float D = 0.0f, X = 0.0f, Y = 0.0f;
        for (int i = 0; i < 256; i++) { D += sd[i]; X += sx[i]; Y += sy[i]; }
        float nq = fmaxf(sqrtf(X), 1e-8f);
        float na = fmaxf(sqrtf(Y), 1e-8f);
        out[b] = D / (nq * na);
    }
}

// ---------------------------------------------------------------------------
// launch
// ---------------------------------------------------------------------------
extern "C" void kernel_launch(void* const* d_in, const int* in_sizes, int n_in,
                              void* d_out, int out_size)
{
    const int*   questions = (const int*)d_in[0];
    const int*   answers   = (const int*)d_in[1];
    const float* emb       = (const float*)d_in[2];
    const float* conv_w    = (const float*)d_in[3];
    const float* conv_b    = (const float*)d_in[4];
    const float* W         = (const float*)d_in[5];
    float*       out       = (float*)d_out;

    (void)in_sizes; (void)n_in; (void)out_size;

    static bool attr_done = false;
    if (!attr_done) {
        cudaFuncSetAttribute(conv_encode_kernel,
                             cudaFuncAttributeMaxDynamicSharedMemorySize, SMEM_CONV);
        cudaFuncSetAttribute(gemm_T_kernel,
                             cudaFuncAttributeMaxDynamicSharedMemorySize, SMEM_T);
        cudaFuncSetAttribute(gemm_G_kernel,
                             cudaFuncAttributeMaxDynamicSharedMemorySize, SMEM_G);
        attr_done = true;
    }

    init_max_kernel<<<(BATCH * LAv + 255) / 256, 256>>>();
    transpose_w_kernel<<<(KCONV * FILT + 255) / 256, 256>>>(conv_w);

    conv_encode_kernel<<<dim3(5, FILT / 80, BATCH), 256, SMEM_CONV>>>(
        questions, answers, emb, conv_b);

    gemm_T_kernel<<<dim3(FILT / 80, 1, BATCH), 256, SMEM_T>>>(W);
    gemm_G_kernel<<<dim3(LAv / 64, 1, BATCH), 256, SMEM_G>>>();

    finalize_kernel<<<BATCH, 256>>>(out);
}

// round 6
// speedup vs baseline: 6.6961x; 1.0248x over previous
#include <cuda_runtime.h>
#include <math.h>

#define BATCH 128
#define LQv   128
#define LAv   512
#define EMBD  300
#define FILT  400
#define EPAD  320
#define KCONV (3 * EPAD)   // 960

// ---- scratch (static __device__: no allocations allowed) ----
__device__ float    g_Q[BATCH * LQv * FILT];     // [b*LQ+t][f]
__device__ float    g_A[BATCH * LAv * FILT];     // [b*LA+t][f]
__device__ float    g_T[BATCH * LQv * FILT];     // [b*LQ+q][g]
__device__ unsigned g_Bw[KCONV * FILT];          // conv weights [k'][f], tf32 bits, zero-padded
__device__ unsigned g_mq[BATCH * LQv];
__device__ unsigned g_ma[BATCH * LAv];

__device__ __forceinline__ unsigned enc_f(float f) {
    int i = __float_as_int(f);
    return (unsigned)(i ^ ((i >> 31) | 0x80000000));
}
__device__ __forceinline__ float dec_f(unsigned u) {
    int i = (u & 0x80000000u) ? (int)(u ^ 0x80000000u) : ~(int)u;
    return __int_as_float(i);
}
__device__ __forceinline__ unsigned f2tf(float f) {
    unsigned u;
    asm("cvt.rna.tf32.f32 %0, %1;" : "=r"(u) : "f"(f));
    return u;
}
__device__ __forceinline__ void mma8(float* c, const unsigned* a, const unsigned* b) {
    asm("mma.sync.aligned.m16n8k8.row.col.f32.tf32.tf32.f32 "
        "{%0,%1,%2,%3},{%4,%5,%6,%7},{%8,%9},{%0,%1,%2,%3};"
        : "+f"(c[0]), "+f"(c[1]), "+f"(c[2]), "+f"(c[3])
        : "r"(a[0]), "r"(a[1]), "r"(a[2]), "r"(a[3]), "r"(b[0]), "r"(b[1]));
}
__device__ __forceinline__ void cp16(void* sptr, const void* gptr, int bytes) {
    unsigned s = (unsigned)__cvta_generic_to_shared(sptr);
    asm volatile("cp.async.cg.shared.global [%0], [%1], 16, %2;"
                 :: "r"(s), "l"(gptr), "r"(bytes));
}
__device__ __forceinline__ void cp16f(void* sptr, const void* gptr) {
    unsigned s = (unsigned)__cvta_generic_to_shared(sptr);
    asm volatile("cp.async.cg.shared.global [%0], [%1], 16;"
                 :: "r"(s), "l"(gptr));
}
#define CP_COMMIT() asm volatile("cp.async.commit_group;")
#define CP_WAIT1()  asm volatile("cp.async.wait_group 1;")

// ---------------------------------------------------------------------------
// 0) init max buffers
// ---------------------------------------------------------------------------
__global__ void init_max_kernel() {
    int idx = blockIdx.x * blockDim.x + threadIdx.x;
    unsigned v = enc_f(-2.0f);
    if (idx < BATCH * LQv) g_mq[idx] = v;
    if (idx < BATCH * LAv) g_ma[idx] = v;
}

// ---------------------------------------------------------------------------
// 0b) pre-transpose conv weights
// ---------------------------------------------------------------------------
__global__ void transpose_w_kernel(const float* __restrict__ cw) {
    int idx = blockIdx.x * blockDim.x + threadIdx.x;
    if (idx >= KCONV * FILT) return;
    int kp = idx / FILT, n = idx % FILT;
    int koff = kp / EPAD, e = kp % EPAD;
    float v = (e < EMBD) ? cw[(size_t)n * (EMBD * 3) + e * 3 + koff] : 0.0f;
    g_Bw[idx] = f2tf(v);
}

// ---------------------------------------------------------------------------
// 1) conv encode, tf32 mma, cp.async 2-stage.
//    128 threads, 4 warps (2m x 2n), warp tile 64x40, block 128 tok x 80 filt.
// ---------------------------------------------------------------------------
#define C_KC 32
#define C_NCH (EPAD / C_KC)     // 10
#define E_PITCH 36
#define E_BUF  (130 * E_PITCH)
#define B_PITCH 88
#define B_KOFF (C_KC * B_PITCH)
#define B_BUF  (3 * B_KOFF)
#define SM_E_OFF 136
#define SM_B_OFF (SM_E_OFF + 2 * E_BUF)
#define SMEM_CONV ((SM_B_OFF + 2 * B_BUF) * 4)

__global__ __launch_bounds__(128, 2) void conv_encode_kernel(
    const int* __restrict__ qtok, const int* __restrict__ atok,
    const float* __restrict__ emb, const float* __restrict__ cb)
{
    extern __shared__ unsigned sm[];
    int*      s_tok = (int*)sm;
    unsigned* E     = sm + SM_E_OFF;
    unsigned* Bsm   = sm + SM_B_OFF;

    const int b   = blockIdx.z;
    const int n0  = blockIdx.y * 80;
    const int tid = threadIdx.x;
    const int wid = tid >> 5, lane = tid & 31;
    const int g   = lane >> 2, tig = lane & 3;
    const int wm  = wid & 1,  wn  = wid >> 1;
    const int mwb = wm * 64,  nwb = wn * 40;

    const int* tok;
    float* dst;
    int L, t0;
    if (blockIdx.x == 0) { tok = qtok; dst = g_Q; L = LQv; t0 = 0; }
    else                 { tok = atok; dst = g_A; L = LAv; t0 = (blockIdx.x - 1) * 128; }

    for (int r = tid; r < 130; r += 128) {
        int tg = t0 + r - 1;
        s_tok[r] = (tg >= 0 && tg < L) ? tok[b * L + tg] : 0;
    }
    __syncthreads();

    auto prefetch = [&](int ch, int bs) {
        int ec = ch * C_KC;
        unsigned* Eb = E + bs * E_BUF;
        unsigned* Bb = Bsm + bs * B_BUF;
        for (int i = tid; i < 130 * 8; i += 128) {
            int r = i >> 3, sg = i & 7;
            int e = ec + sg * 4;
            int el = 300 - e; el = el < 0 ? 0 : (el > 4 ? 4 : el);
            int bytes = el * 4;
            const float* src = emb + (bytes ? ((size_t)s_tok[r] * EMBD + e) : 0);
            cp16(&Eb[r * E_PITCH + sg * 4], src, bytes);
        }
        for (int i = tid; i < 3 * C_KC * 20; i += 128) {
            int ko = i / 640; int r2 = i - ko * 640;
            int kc = r2 / 20; int sg = r2 - kc * 20;
            const unsigned* src = g_Bw + (size_t)(ko * EPAD + ec + kc) * FILT + n0 + sg * 4;
            cp16f(&Bb[ko * B_KOFF + kc * B_PITCH + sg * 4], src);
        }
    };

    float c[4][5][4];
#pragma unroll
    for (int i = 0; i < 4; i++)
#pragma unroll
        for (int j = 0; j < 5; j++)
#pragma unroll
            for (int k = 0; k < 4; k++) c[i][j][k] = 0.0f;

    prefetch(0, 0);
    CP_COMMIT();

    for (int ch = 0; ch < C_NCH; ch++) {
        int bs = ch & 1;
        if (ch + 1 < C_NCH) prefetch(ch + 1, bs ^ 1);
        CP_COMMIT();
        CP_WAIT1();
        __syncthreads();

        const unsigned* Eb = E + bs * E_BUF;
        const unsigned* Bb = Bsm + bs * B_BUF;

#pragma unroll
        for (int ko = 0; ko < 3; ko++) {
            const unsigned* Bk = Bb + ko * B_KOFF;
#pragma unroll
            for (int kb = 0; kb < C_KC / 8; kb++) {
                int kk = kb * 8;
                unsigned a[4][4];
#pragma unroll
                for (int ms = 0; ms < 4; ms++) {
                    int row = mwb + ms * 16 + g + ko;
                    a[ms][0] = Eb[(row)     * E_PITCH + kk + tig];
                    a[ms][1] = Eb[(row + 8) * E_PITCH + kk + tig];
                    a[ms][2] = Eb[(row)     * E_PITCH + kk + tig + 4];
                    a[ms][3] = Eb[(row + 8) * E_PITCH + kk + tig + 4];
                }
#pragma unroll
                for (int ns = 0; ns < 5; ns++) {
                    unsigned bf[2];
                    int nb = nwb + ns * 8 + g;
                    bf[0] = Bk[(kk + tig)     * B_PITCH + nb];
                    bf[1] = Bk[(kk + tig + 4) * B_PITCH + nb];
#pragma unroll
                    for (int ms = 0; ms < 4; ms++)
                        mma8(c[ms][ns], a[ms], bf);
                }
            }
        }
        __syncthreads();
    }

#pragma unroll
    for (int ms = 0; ms < 4; ms++) {
#pragma unroll
        for (int ns = 0; ns < 5; ns++) {
            int col = n0 + nwb + ns * 8 + 2 * tig;
            float2 bias = *(const float2*)&cb[col];
            int row0 = t0 + mwb + ms * 16 + g;
            *(float2*)&dst[((size_t)b * L + row0) * FILT + col] =
                make_float2(c[ms][ns][0] + bias.x, c[ms][ns][1] + bias.y);
            *(float2*)&dst[((size_t)b * L + row0 + 8) * FILT + col] =
                make_float2(c[ms][ns][2] + bias.x, c[ms][ns][3] + bias.y);
        }
    }
}

// ---------------------------------------------------------------------------
// 2) T = Qm @ W : M=128, N=400 (5 x 80), K=400.
//    128 threads, 4 warps (2m x 2n), warp tile 64x40. cp.async 2-stage.
// ---------------------------------------------------------------------------
#define T_KC 40
#define T_AP 44
#define T_BP 88
#define T_ABUF (128 * T_AP)
#define T_BOFF (2 * T_ABUF)
#define T_BBUF (T_KC * T_BP)
#define SMEM_T ((T_BOFF + 2 * T_BBUF) * 4)

__global__ __launch_bounds__(128, 2) void gemm_T_kernel(const float* __restrict__ W)
{
    extern __shared__ unsigned sm[];
    unsigned* Asm = sm;
    unsigned* Bsm = sm + T_BOFF;

    const int b  = blockIdx.z;
    const int n0 = blockIdx.x * 80;
    const int tid  = threadIdx.x;
    const int wid  = tid >> 5, lane = tid & 31;
    const int g    = lane >> 2, tig = lane & 3;
    const int wm   = wid & 1,  wn  = wid >> 1;
    const int mwb  = wm * 64, nwb = wn * 40;

    const float* Qb = g_Q + (size_t)b * LQv * FILT;

    auto prefetch = [&](int ch, int bs) {
        int k0 = ch * T_KC;
        unsigned* Ab = Asm + bs * T_ABUF;
        unsigned* Bb = Bsm + bs * T_BBUF;
#pragma unroll
        for (int it = 0; it < 10; it++) {
            int i = tid + it * 128;                 // 1280 = 128 m x 10 k4
            int m = i / 10, k4 = i - m * 10;
            cp16f(&Ab[m * T_AP + k4 * 4], Qb + (size_t)m * FILT + k0 + k4 * 4);
        }
        for (int i = tid; i < T_KC * 20; i += 128) { // 800 = 40 k x 20 n4
            int kc = i / 20, sg = i - kc * 20;
            cp16f(&Bb[kc * T_BP + sg * 4], W + (size_t)(k0 + kc) * FILT + n0 + sg * 4);
        }
    };

    float c[4][5][4];
#pragma unroll
    for (int i = 0; i < 4; i++)
#pragma unroll
        for (int j = 0; j < 5; j++)
#pragma unroll
            for (int k = 0; k < 4; k++) c[i][j][k] = 0.0f;

    prefetch(0, 0);
    CP_COMMIT();

    for (int ch = 0; ch < FILT / T_KC; ch++) {
        int bs = ch & 1;
        if (ch + 1 < FILT / T_KC) prefetch(ch + 1, bs ^ 1);
        CP_COMMIT();
        CP_WAIT1();
        __syncthreads();

        const unsigned* Ab = Asm + bs * T_ABUF;
        const unsigned* Bb = Bsm + bs * T_BBUF;

#pragma unroll
        for (int kb = 0; kb < T_KC / 8; kb++) {
            int kk = kb * 8;
            unsigned a[4][4];
#pragma unroll
            for (int ms = 0; ms < 4; ms++) {
                int row = mwb + ms * 16 + g;
                a[ms][0] = Ab[(row)     * T_AP + kk + tig];
                a[ms][1] = Ab[(row + 8) * T_AP + kk + tig];
                a[ms][2] = Ab[(row)     * T_AP + kk + tig + 4];
                a[ms][3] = Ab[(row + 8) * T_AP + kk + tig + 4];
            }
#pragma unroll
            for (int ns = 0; ns < 5; ns++) {
                unsigned bf[2];
                int nb = nwb + ns * 8 + g;
                bf[0] = Bb[(kk + tig)     * T_BP + nb];
                bf[1] = Bb[(kk + tig + 4) * T_BP + nb];
#pragma unroll
                for (int ms = 0; ms < 4; ms++)
                    mma8(c[ms][ns], a[ms], bf);
            }
        }
        __syncthreads();
    }

#pragma unroll
    for (int ms = 0; ms < 4; ms++) {
#pragma unroll
        for (int ns = 0; ns < 5; ns++) {
            int col = n0 + nwb + ns * 8 + 2 * tig;
            int row0 = mwb + ms * 16 + g;
            *(float2*)&g_T[((size_t)b * LQv + row0) * FILT + col] =
                make_float2(c[ms][ns][0], c[ms][ns][1]);
            *(float2*)&g_T[((size_t)b * LQv + row0 + 8) * FILT + col] =
                make_float2(c[ms][ns][2], c[ms][ns][3]);
        }
    }
}

// ---------------------------------------------------------------------------
// 3) G = tanh(T @ A^T) fused row/col max. M=128(q), N=512 (4 x 128), K=400.
//    256 threads, 8 warps (2m x 4n), warp tile 64x32. cp.async 2-stage.
// ---------------------------------------------------------------------------
#define G_KC 40
#define G_AP 44
#define G_ABUF (128 * G_AP)          // 5632
#define G_BOFF (2 * G_ABUF)          // 11264
#define G_BBUF (128 * G_AP)          // 5632
#define G_RED  (G_BOFF + 2 * G_BBUF) // 22528
#define SMEM_G ((G_RED + 256) * 4)

__global__ __launch_bounds__(256, 2) void gemm_G_kernel()
{
    extern __shared__ unsigned sm[];
    unsigned* Asm  = sm;
    unsigned* Bsm  = sm + G_BOFF;
    unsigned* srow = sm + G_RED;        // 128
    unsigned* scol = sm + G_RED + 128;  // 128

    const int b  = blockIdx.z;
    const int a0 = blockIdx.x * 128;
    const int tid  = threadIdx.x;
    const int wid  = tid >> 5, lane = tid & 31;
    const int g    = lane >> 2, tig = lane & 3;
    const int wm   = wid & 1,  wn  = wid >> 1;
    const int mwb  = wm * 64, nwb = wn * 32;

    if (tid < 128) { srow[tid] = enc_f(-2.0f); scol[tid] = enc_f(-2.0f); }

    const float* Tb  = g_T + (size_t)b * LQv * FILT;
    const float* Ab0 = g_A + ((size_t)b * LAv + a0) * FILT;

    auto prefetch = [&](int ch, int bs) {
        int k0 = ch * G_KC;
        unsigned* Abuf = Asm + bs * G_ABUF;
        unsigned* Bbuf = Bsm + bs * G_BBUF;
#pragma unroll
        for (int it = 0; it < 5; it++) {
            int i = tid + it * 256;                  // 1280 = 128 q x 10 k4
            int m = i / 10, k4 = i - m * 10;
            cp16f(&Abuf[m * G_AP + k4 * 4], Tb + (size_t)m * FILT + k0 + k4 * 4);
        }
#pragma unroll
        for (int it = 0; it < 5; it++) {
            int i = tid + it * 256;                  // 1280 = 128 a x 10 k4
            int n = i / 10, k4 = i - n * 10;
            cp16f(&Bbuf[n * G_AP + k4 * 4], Ab0 + (size_t)n * FILT + k0 + k4 * 4);
        }
    };

    float c[4][4][4];
#pragma unroll
    for (int i = 0; i < 4; i++)
#pragma unroll
        for (int j = 0; j < 4; j++)
#pragma unroll
            for (int k = 0; k < 4; k++) c[i][j][k] = 0.0f;

    prefetch(0, 0);
    CP_COMMIT();

    for (int ch = 0; ch < FILT / G_KC; ch++) {
        int bs = ch & 1;
        if (ch + 1 < FILT / G_KC) prefetch(ch + 1, bs ^ 1);
        CP_COMMIT();
        CP_WAIT1();
        __syncthreads();

        const unsigned* Abuf = Asm + bs * G_ABUF;
        const unsigned* Bbuf = Bsm + bs * G_BBUF;

#pragma unroll
        for (int kb = 0; kb < G_KC / 8; kb++) {
            int kk = kb * 8;
            unsigned a[4][4];
#pragma unroll
            for (int ms = 0; ms < 4; ms++) {
                int row = mwb + ms * 16 + g;
                a[ms][0] = Abuf[(row)     * G_AP + kk + tig];
                a[ms][1] = Abuf[(row + 8) * G_AP + kk + tig];
                a[ms][2] = Abuf[(row)     * G_AP + kk + tig + 4];
                a[ms][3] = Abuf[(row + 8) * G_AP + kk + tig + 4];
            }
#pragma unroll
            for (int ns = 0; ns < 4; ns++) {
                unsigned bf[2];
                int nb = nwb + ns * 8 + g;
                bf[0] = Bbuf[nb * G_AP + kk + tig];
                bf[1] = Bbuf[nb * G_AP + kk + tig + 4];
#pragma unroll
                for (int ms = 0; ms < 4; ms++)
                    mma8(c[ms][ns], a[ms], bf);
            }
        }
        __syncthreads();
    }

    float tv[4][4][4];
#pragma unroll
    for (int ms = 0; ms < 4; ms++)
#pragma unroll
        for (int ns = 0; ns < 4; ns++)
#pragma unroll
            for (int k = 0; k < 4; k++) tv[ms][ns][k] = tanhf(c[ms][ns][k]);

#pragma unroll
    for (int ms = 0; ms < 4; ms++) {
        float r0 = -2.0f, r1 = -2.0f;
#pragma unroll
        for (int ns = 0; ns < 4; ns++) {
            r0 = fmaxf(r0, fmaxf(tv[ms][ns][0], tv[ms][ns][1]));
            r1 = fmaxf(r1, fmaxf(tv[ms][ns][2], tv[ms][ns][3]));
        }
        atomicMax(&srow[mwb + ms * 16 + g],     enc_f(r0));
        atomicMax(&srow[mwb + ms * 16 + g + 8], enc_f(r1));
    }
#pragma unroll
    for (int ns = 0; ns < 4; ns++) {
        float c0 = -2.0f, c1 = -2.0f;
#pragma unroll
        for (int ms = 0; ms < 4; ms++) {
            c0 = fmaxf(c0, fmaxf(tv[ms][ns][0], tv[ms][ns][2]));
            c1 = fmaxf(c1, fmaxf(tv[ms][ns][1], tv[ms][ns][3]));
        }
        int nb = nwb + ns * 8 + 2 * tig;
        atomicMax(&scol[nb],     enc_f(c0));
        atomicMax(&scol[nb + 1], enc_f(c1));
    }
    __syncthreads();

    if (tid < 128) {
        atomicMax(&g_mq[b * LQv + tid], srow[tid]);
        atomicMax(&g_ma[b * LAv + a0 + tid], scol[tid]);
    }
}

// ---------------------------------------------------------------------------
// 4) per-batch finalize (softmax over maxes, pooling, cosine)
// ---------------------------------------------------------------------------
__device__ __forceinline__ float warp_max(float v) {
#pragma unroll
    for (int o = 16; o > 0; o >>= 1) v = fmaxf(v, __shfl_xor_sync(0xffffffffu, v, o));
    return v;
}
__device__ __forceinline__ float warp_sum(float v) {
#pragma unroll
    for (int o = 16; o > 0; o >>= 1) v += __shfl_xor_sync(0xffffffffu, v, o);
    return v;
}

__global__ __launch_bounds__(256) void finalize_kernel(float* __restrict__ out)
{
    __shared__ float sq[LQv], sa[LAv], rq[FILT], ra[FILT];
    __shared__ float smax[2], ssum[2];
    __shared__ float sd[256], sx[256], sy[256];

    const int b = blockIdx.x;
    const int tid = threadIdx.x;
    const int lane = tid & 31;

    for (int q = tid; q < LQv; q += 256) sq[q] = dec_f(g_mq[b * LQv + q]);
    for (int a = tid; a < LAv; a += 256) sa[a] = dec_f(g_ma[b * LAv + a]);
    __syncthreads();

    if (tid < 32) {
        float m = -1e30f;
        for (int q = lane; q < LQv; q += 32) m = fmaxf(m, sq[q]);
        m = warp_max(m);
        if (lane == 0) smax[0] = m;
    } else if (tid < 64) {
        float m = -1e30f;
        for (int a = lane; a < LAv; a += 32) m = fmaxf(m, sa[a]);
        m = warp_max(m);
        if (lane == 0) smax[1] = m;
    }
    __syncthreads();
    for (int q = tid; q < LQv; q += 256) sq[q] = expf(sq[q] - smax[0]);
    for (int a = tid; a < LAv; a += 256) sa[a] = expf(sa[a] - smax[1]);
    __syncthreads();
    if (tid < 32) {
        float s = 0.0f;
        for (int q = lane; q < LQv; q += 32) s += sq[q];
        s = warp_sum(s);
        if (lane == 0) ssum[0] = s;
    } else if (tid < 64) {
        float s = 0.0f;
        for (int a = lane; a < LAv; a += 32) s += sa[a];
        s = warp_sum(s);
        if (lane == 0) ssum[1] = s;
    }
    __syncthreads();
    {
        float invq = 1.0f / ssum[0], inva = 1.0f / ssum[1];
        for (int q = tid; q < LQv; q += 256) sq[q] *= invq;
        for (int a = tid; a < LAv; a += 256) sa[a] *= inva;
    }
    __syncthreads();

    for (int f = tid; f < FILT; f += 256) {
        const float* qp = g_Q + (size_t)b * LQv * FILT + f;
        float acc = 0.0f;
#pragma unroll 8
        for (int q = 0; q < LQv; q++) acc += qp[(size_t)q * FILT] * sq[q];
        rq[f] = acc;
    }
    for (int f = tid; f < FILT; f += 256) {
        const float* ap = g_A + (size_t)b * LAv * FILT + f;
        float acc = 0.0f;
#pragma unroll 8
        for (int a = 0; a < LAv; a++) acc += ap[(size_t)a * FILT] * sa[a];
        ra[f] = acc;
    }
    __syncthreads();

    float d = 0.0f, x = 0.0f, y = 0.0f;
    for (int f = tid; f < FILT; f += 256) {
        d += rq[f] * ra[f];
        x += rq[f] * rq[f];
        y += ra[f] * ra[f];
    }
    sd[tid] = d; sx[tid] = x; sy[tid] = y;
    __syncthreads();
    if (tid == 0) {
        float D = 0.0f, X = 0.0f, Y = 0.0f;
        for (int i = 0; i < 256; i++) { D += sd[i]; X += sx[i]; Y += sy[i]; }
        float nq = fmaxf(sqrtf(X), 1e-8f);
        float na = fmaxf(sqrtf(Y), 1e-8f);
        out[b] = D / (nq * na);
    }
}

// ---------------------------------------------------------------------------
// launch
// ---------------------------------------------------------------------------
extern "C" void kernel_launch(void* const* d_in, const int* in_sizes, int n_in,
                              void* d_out, int out_size)
{
    const int*   questions = (const int*)d_in[0];
    const int*   answers   = (const int*)d_in[1];
    const float* emb       = (const float*)d_in[2];
    const float* conv_w    = (const float*)d_in[3];
    const float* conv_b    = (const float*)d_in[4];
    const float* W         = (const float*)d_in[5];
    float*       out       = (float*)d_out;

    (void)in_sizes; (void)n_in; (void)out_size;

    static bool attr_done = false;
    if (!attr_done) {
        cudaFuncSetAttribute(conv_encode_kernel,
                             cudaFuncAttributeMaxDynamicSharedMemorySize, SMEM_CONV);
        cudaFuncSetAttribute(gemm_T_kernel,
                             cudaFuncAttributeMaxDynamicSharedMemorySize, SMEM_T);
        cudaFuncSetAttribute(gemm_G_kernel,
                             cudaFuncAttributeMaxDynamicSharedMemorySize, SMEM_G);
        attr_done = true;
    }

    init_max_kernel<<<(BATCH * LAv + 255) / 256, 256>>>();
    transpose_w_kernel<<<(KCONV * FILT + 255) / 256, 256>>>(conv_w);

    conv_encode_kernel<<<dim3(5, FILT / 80, BATCH), 128, SMEM_CONV>>>(
        questions, answers, emb, conv_b);

    gemm_T_kernel<<<dim3(FILT / 80, 1, BATCH), 128, SMEM_T>>>(W);
    gemm_G_kernel<<<dim3(LAv / 128, 1, BATCH), 256, SMEM_G>>>();

    finalize_kernel<<<BATCH, 256>>>(out);
}